// round 1
// baseline (speedup 1.0000x reference)
#include <cuda_runtime.h>
#include <math.h>

#define E_DIM 2048
#define SEQ 2048
#define NBATCH 2
#define NHEAD 16
#define HD 128
#define MROWS (NBATCH * SEQ) /* 4096 */

// ---------------- scratch (device globals; no allocation allowed) ----------
__device__ float g_q[MROWS * E_DIM];
__device__ float g_k[MROWS * E_DIM];
__device__ float g_v[MROWS * E_DIM];
__device__ float g_attn[MROWS * E_DIM];
__device__ float g_cos[SEQ * (HD / 2)];
__device__ float g_sin[SEQ * (HD / 2)];

// ---------------- RoPE table --------------------------------------------
// Matches reference: inv_freq in fp32, angle = float(pos) * inv_freq (fp32
// rounded multiply), then accurate cos/sin of that fp32 value (double trig,
// round to float ~ correctly rounded; immune to --use_fast_math).
__global__ void rope_init_kernel() {
    int idx = blockIdx.x * blockDim.x + threadIdx.x;
    if (idx >= SEQ * (HD / 2)) return;
    int pos = idx / (HD / 2);
    int i = idx % (HD / 2);
    double invd = pow(10000.0, -(double)(2 * i) / (double)HD);
    float inv = (float)invd;
    float ang = (float)pos * inv;
    g_cos[idx] = (float)cos((double)ang);
    g_sin[idx] = (float)sin((double)ang);
}

// ---------------- TN SGEMM: C[m,n] = sum_k A[m,k] * B[n,k] ----------------
// M=4096, N=2048, K=2048 fixed. 128x128 block tile, 8x8 thread tile, BK=16.
#define BM 128
#define BN 128
#define BK 16
#define SM_STRIDE 132  // padded (bank-conflict-free transposed stores/reads)

__device__ __forceinline__ void gemm_body(const float* __restrict__ A,
                                          const float* __restrict__ B,
                                          float* __restrict__ C, bool rope) {
    __shared__ float As[BK][SM_STRIDE];
    __shared__ float Bs[BK][SM_STRIDE];

    int tid = threadIdx.x;
    int tx = tid & 15;
    int ty = tid >> 4;
    int m0 = blockIdx.y * BM;
    int n0 = blockIdx.x * BN;

    float acc[8][8];
#pragma unroll
    for (int i = 0; i < 8; i++)
#pragma unroll
        for (int j = 0; j < 8; j++) acc[i][j] = 0.f;

    for (int k0 = 0; k0 < E_DIM; k0 += BK) {
#pragma unroll
        for (int it = 0; it < 2; it++) {
            int l = tid + it * 256;
            int row = l >> 2;        // 0..127
            int kv = (l & 3) * 4;    // 0,4,8,12
            float4 av = *(const float4*)&A[(size_t)(m0 + row) * E_DIM + k0 + kv];
            float4 bv = *(const float4*)&B[(size_t)(n0 + row) * E_DIM + k0 + kv];
            As[kv + 0][row] = av.x; As[kv + 1][row] = av.y;
            As[kv + 2][row] = av.z; As[kv + 3][row] = av.w;
            Bs[kv + 0][row] = bv.x; Bs[kv + 1][row] = bv.y;
            Bs[kv + 2][row] = bv.z; Bs[kv + 3][row] = bv.w;
        }
        __syncthreads();
#pragma unroll
        for (int kk = 0; kk < BK; kk++) {
            float ra[8], rb[8];
#pragma unroll
            for (int i = 0; i < 8; i++) ra[i] = As[kk][ty * 8 + i];
#pragma unroll
            for (int j = 0; j < 8; j++) rb[j] = Bs[kk][tx * 8 + j];
#pragma unroll
            for (int i = 0; i < 8; i++)
#pragma unroll
                for (int j = 0; j < 8; j++) acc[i][j] += ra[i] * rb[j];
        }
        __syncthreads();
    }

    // epilogue (+ optional interleaved RoPE; 8-col tile is pair-aligned)
#pragma unroll
    for (int i = 0; i < 8; i++) {
        int m = m0 + ty * 8 + i;
        float out[8];
        if (rope) {
            int pos = m & (SEQ - 1);
#pragma unroll
            for (int j = 0; j < 8; j += 2) {
                int n = n0 + tx * 8 + j;
                int pi = (n & (HD - 1)) >> 1;
                float c = g_cos[pos * (HD / 2) + pi];
                float s = g_sin[pos * (HD / 2) + pi];
                float x1 = acc[i][j], x2 = acc[i][j + 1];
                out[j] = x1 * c - x2 * s;
                out[j + 1] = x1 * s + x2 * c;
            }
        } else {
#pragma unroll
            for (int j = 0; j < 8; j++) out[j] = acc[i][j];
        }
        *(float4*)&C[(size_t)m * E_DIM + n0 + tx * 8] =
            make_float4(out[0], out[1], out[2], out[3]);
        *(float4*)&C[(size_t)m * E_DIM + n0 + tx * 8 + 4] =
            make_float4(out[4], out[5], out[6], out[7]);
    }
}

__global__ __launch_bounds__(256) void gemm_qkv_kernel(
    const float* __restrict__ X, const float* __restrict__ Wq,
    const float* __restrict__ Wk, const float* __restrict__ Wv) {
    int z = blockIdx.z;
    const float* B = (z == 0) ? Wq : (z == 1) ? Wk : Wv;
    float* C = (z == 0) ? g_q : (z == 1) ? g_k : g_v;
    gemm_body(X, B, C, z < 2);
}

__global__ __launch_bounds__(256) void gemm_out_kernel(
    const float* __restrict__ Wo, float* __restrict__ out) {
    gemm_body(g_attn, Wo, out, false);
}

// ---------------- Flash attention (fp32, causal) --------------------------
// Block: one (b,h, q-tile of 64 rows). 256 threads: thread = (qr=tid>>2, dg=tid&3),
// owns O[qr, dg*32 .. dg*32+32). K/V tiles of 64 rows iterate causally.
#define FA_BM 64
#define FA_BN 64
#define QSTR 132   // padded row stride for Q/K/V tiles (floats)
#define PSTR 65    // padded row stride for P tile

#define FA_SMEM ((3 * FA_BM * QSTR + FA_BM * PSTR) * 4) /* 118016 bytes */

__global__ __launch_bounds__(256) void flash_kernel() {
    extern __shared__ float sm[];
    float* Qs = sm;
    float* Ks = Qs + FA_BM * QSTR;
    float* Vs = Ks + FA_BM * QSTR;
    float* Ps = Vs + FA_BM * QSTR;

    int qt = (gridDim.x - 1) - blockIdx.x;  // heavy tiles scheduled first
    int bh = blockIdx.y;
    int b = bh >> 4;
    int h = bh & 15;
    int tid = threadIdx.x;
    int qr = tid >> 2;
    int dg = tid & 3;

    const float* qbase = g_q + (size_t)b * SEQ * E_DIM + (size_t)h * HD;
    const float* kbase = g_k + (size_t)b * SEQ * E_DIM + (size_t)h * HD;
    const float* vbase = g_v + (size_t)b * SEQ * E_DIM + (size_t)h * HD;

    // load Q tile (64 x 128)
#pragma unroll
    for (int it = 0; it < 8; it++) {
        int l = tid + it * 256;
        int row = l >> 5;
        int c4 = (l & 31) * 4;
        *(float4*)&Qs[row * QSTR + c4] =
            *(const float4*)&qbase[(size_t)(qt * FA_BM + row) * E_DIM + c4];
    }

    float acc[32];
#pragma unroll
    for (int d = 0; d < 32; d++) acc[d] = 0.f;
    float m_i = -1e30f, l_i = 0.f;
    const float scale = 0.08838834764831845f;  // 1/sqrt(128)
    int qg = qt * FA_BM + qr;

    for (int kt = 0; kt <= qt; kt++) {
        __syncthreads();  // previous iter's K/V/P reads done
#pragma unroll
        for (int it = 0; it < 8; it++) {
            int l = tid + it * 256;
            int row = l >> 5;
            int c4 = (l & 31) * 4;
            *(float4*)&Ks[row * QSTR + c4] =
                *(const float4*)&kbase[(size_t)(kt * FA_BN + row) * E_DIM + c4];
            *(float4*)&Vs[row * QSTR + c4] =
                *(const float4*)&vbase[(size_t)(kt * FA_BN + row) * E_DIM + c4];
        }
        __syncthreads();

        // scores: this thread computes row qr vs 16 k-cols j = jj*4+dg
        float sreg[16];
#pragma unroll
        for (int jj = 0; jj < 16; jj++) sreg[jj] = 0.f;
        for (int d4 = 0; d4 < HD; d4 += 4) {
            float4 qv = *(float4*)&Qs[qr * QSTR + d4];
#pragma unroll
            for (int jj = 0; jj < 16; jj++) {
                int j = jj * 4 + dg;
                float4 kv = *(float4*)&Ks[j * QSTR + d4];
                sreg[jj] += qv.x * kv.x + qv.y * kv.y + qv.z * kv.z + qv.w * kv.w;
            }
        }

        // scale + causal mask + tile row-max
        float mtile = -1e30f;
#pragma unroll
        for (int jj = 0; jj < 16; jj++) {
            int kg = kt * FA_BN + jj * 4 + dg;
            float sv = sreg[jj] * scale;
            sv = (kg <= qg) ? sv : -1e30f;
            sreg[jj] = sv;
            mtile = fmaxf(mtile, sv);
        }
        mtile = fmaxf(mtile, __shfl_xor_sync(0xffffffffu, mtile, 1));
        mtile = fmaxf(mtile, __shfl_xor_sync(0xffffffffu, mtile, 2));
        float m_new = fmaxf(m_i, mtile);

        float lsum = 0.f;
#pragma unroll
        for (int jj = 0; jj < 16; jj++) {
            float p = __expf(sreg[jj] - m_new);
            sreg[jj] = p;
            lsum += p;
        }
        lsum += __shfl_xor_sync(0xffffffffu, lsum, 1);
        lsum += __shfl_xor_sync(0xffffffffu, lsum, 2);

        float alpha = __expf(m_i - m_new);
        m_i = m_new;
        l_i = l_i * alpha + lsum;
#pragma unroll
        for (int d = 0; d < 32; d++) acc[d] *= alpha;

        // publish P row (row qr only touched by this warp's 4 lanes)
#pragma unroll
        for (int jj = 0; jj < 16; jj++) Ps[qr * PSTR + jj * 4 + dg] = sreg[jj];
        __syncwarp();

        // O += P @ V  (this thread: row qr, d-range dg*32..+32)
#pragma unroll 4
        for (int j = 0; j < FA_BN; j++) {
            float p = Ps[qr * PSTR + j];
            const float4* vrow = (const float4*)&Vs[j * QSTR + dg * 32];
#pragma unroll
            for (int d4 = 0; d4 < 8; d4++) {
                float4 vv = vrow[d4];
                acc[d4 * 4 + 0] += p * vv.x;
                acc[d4 * 4 + 1] += p * vv.y;
                acc[d4 * 4 + 2] += p * vv.z;
                acc[d4 * 4 + 3] += p * vv.w;
            }
        }
        __syncwarp();
    }

    float inv_l = 1.0f / l_i;
    float* obase = g_attn + (size_t)b * SEQ * E_DIM +
                   (size_t)(qt * FA_BM + qr) * E_DIM + (size_t)h * HD + dg * 32;
#pragma unroll
    for (int d4 = 0; d4 < 8; d4++) {
        float4 o;
        o.x = acc[d4 * 4 + 0] * inv_l;
        o.y = acc[d4 * 4 + 1] * inv_l;
        o.z = acc[d4 * 4 + 2] * inv_l;
        o.w = acc[d4 * 4 + 3] * inv_l;
        *(float4*)&obase[d4 * 4] = o;
    }
}

// ---------------- launcher -------------------------------------------------
extern "C" void kernel_launch(void* const* d_in, const int* in_sizes, int n_in,
                              void* d_out, int out_size) {
    const float* x = (const float*)d_in[0];
    const float* Wq = (const float*)d_in[1];
    const float* Wk = (const float*)d_in[2];
    const float* Wv = (const float*)d_in[3];
    const float* Wo = (const float*)d_in[4];
    float* out = (float*)d_out;

    cudaFuncSetAttribute(flash_kernel, cudaFuncAttributeMaxDynamicSharedMemorySize,
                         FA_SMEM);

    rope_init_kernel<<<(SEQ * (HD / 2) + 255) / 256, 256>>>();

    dim3 gqkv(E_DIM / BN, MROWS / BM, 3);
    gemm_qkv_kernel<<<gqkv, 256>>>(x, Wq, Wk, Wv);

    dim3 gfa(SEQ / FA_BM, NBATCH * NHEAD);
    flash_kernel<<<gfa, 256, FA_SMEM>>>();

    dim3 gout(E_DIM / BN, MROWS / BM);
    gemm_out_kernel<<<gout, 256>>>(Wo, out);
}

// round 5
// speedup vs baseline: 1.2143x; 1.2143x over previous
#include <cuda_runtime.h>
#include <cuda_bf16.h>
#include <math.h>
#include <stdint.h>

#define E_DIM 2048
#define SEQ 2048
#define NBATCH 2
#define NHEAD 16
#define HD 128
#define MROWS (NBATCH * SEQ) /* 4096 */

// ---------------- scratch (device globals; no allocation allowed) ----------
__device__ float g_q[MROWS * E_DIM];
__device__ float g_k[MROWS * E_DIM];
__device__ float g_v[MROWS * E_DIM];
__device__ __nv_bfloat16 g_x_hi[MROWS * E_DIM];
__device__ __nv_bfloat16 g_x_lo[MROWS * E_DIM];
__device__ __nv_bfloat16 g_w_hi[4 * E_DIM * E_DIM];
__device__ __nv_bfloat16 g_w_lo[4 * E_DIM * E_DIM];
__device__ __nv_bfloat16 g_attn_hi[MROWS * E_DIM];
__device__ __nv_bfloat16 g_attn_lo[MROWS * E_DIM];
__device__ float g_cos[SEQ * (HD / 2)];
__device__ float g_sin[SEQ * (HD / 2)];

// ---------------- helpers ----------------------------------------------------
// D (fp32) += A (bf16 16x16) * B (bf16 16x8)
__device__ __forceinline__ void mma_bf16(float* d, const uint32_t* a,
                                         const uint32_t* b) {
    asm volatile(
        "mma.sync.aligned.m16n8k16.row.col.f32.bf16.bf16.f32 "
        "{%0,%1,%2,%3}, {%4,%5,%6,%7}, {%8,%9}, {%0,%1,%2,%3};"
        : "+f"(d[0]), "+f"(d[1]), "+f"(d[2]), "+f"(d[3])
        : "r"(a[0]), "r"(a[1]), "r"(a[2]), "r"(a[3]), "r"(b[0]), "r"(b[1]));
}

// ---------------- RoPE table ------------------------------------------------
__global__ void rope_init_kernel() {
    int idx = blockIdx.x * blockDim.x + threadIdx.x;
    if (idx >= SEQ * (HD / 2)) return;
    int pos = idx / (HD / 2);
    int i = idx % (HD / 2);
    double invd = pow(10000.0, -(double)(2 * i) / (double)HD);
    float inv = (float)invd;
    float ang = (float)pos * inv;
    g_cos[idx] = (float)cos((double)ang);
    g_sin[idx] = (float)sin((double)ang);
}

// ---------------- fp32 -> split bf16 conversion -----------------------------
// NOTE: device globals are referenced INSIDE device code only (host-side
// references to __device__ symbols yield invalid pointers — the R3/R4 bug).
__device__ __forceinline__ void split_store(__nv_bfloat162* hi,
                                            __nv_bfloat162* lo, int i,
                                            float4 v) {
    __nv_bfloat16 h0 = __float2bfloat16(v.x);
    __nv_bfloat16 h1 = __float2bfloat16(v.y);
    __nv_bfloat16 h2 = __float2bfloat16(v.z);
    __nv_bfloat16 h3 = __float2bfloat16(v.w);
    hi[i * 2 + 0] = __nv_bfloat162(h0, h1);
    hi[i * 2 + 1] = __nv_bfloat162(h2, h3);
    lo[i * 2 + 0] = __nv_bfloat162(__float2bfloat16(v.x - __bfloat162float(h0)),
                                   __float2bfloat16(v.y - __bfloat162float(h1)));
    lo[i * 2 + 1] = __nv_bfloat162(__float2bfloat16(v.z - __bfloat162float(h2)),
                                   __float2bfloat16(v.w - __bfloat162float(h3)));
}

__global__ void convert_x_kernel(const float4* __restrict__ src) {
    int i = blockIdx.x * blockDim.x + threadIdx.x;
    if (i >= MROWS * E_DIM / 4) return;
    split_store((__nv_bfloat162*)g_x_hi, (__nv_bfloat162*)g_x_lo, i, src[i]);
}

__global__ void convert_w_kernel(const float4* __restrict__ src, int z) {
    int i = blockIdx.x * blockDim.x + threadIdx.x;
    if (i >= E_DIM * E_DIM / 4) return;
    split_store((__nv_bfloat162*)(g_w_hi + (size_t)z * E_DIM * E_DIM),
                (__nv_bfloat162*)(g_w_lo + (size_t)z * E_DIM * E_DIM), i, src[i]);
}

// ---------------- HMMA GEMM: C[m,n] = sum_k A[m,k]*B[n,k] -------------------
// 3x-bf16 split (hi*hi + hi*lo + lo*hi). 128x128 CTA tile, BK=16.
// Fragments loaded with direct 4-byte LDS at the PTX-specified coordinates.
#define GBM 128
#define GBN 128
#define GBK 16
#define NCHUNK (E_DIM / GBK) /* 128 */
#define BSTR 48                      /* smem row stride in BYTES (24 bf16) */
#define TILE_BYTES (128 * BSTR)      /* 6144 */
#define STAGE_BYTES (4 * TILE_BYTES) /* 24576: Ahi,Alo,Bhi,Blo */
#define GEMM_SMEM (2 * STAGE_BYTES)  /* 49152 */

__device__ __forceinline__ void load_chunk_g(
    const __nv_bfloat16* __restrict__ Ahi, const __nv_bfloat16* __restrict__ Alo,
    const __nv_bfloat16* __restrict__ Bhi, const __nv_bfloat16* __restrict__ Blo,
    int m0, int n0, int k0, int tid, uint4 r[4]) {
    int row = tid >> 1;          // 0..127
    int ce = (tid & 1) * 8;      // element offset within 16-wide chunk row
    r[0] = *(const uint4*)(Ahi + (size_t)(m0 + row) * E_DIM + k0 + ce);
    r[1] = *(const uint4*)(Alo + (size_t)(m0 + row) * E_DIM + k0 + ce);
    r[2] = *(const uint4*)(Bhi + (size_t)(n0 + row) * E_DIM + k0 + ce);
    r[3] = *(const uint4*)(Blo + (size_t)(n0 + row) * E_DIM + k0 + ce);
}

__device__ __forceinline__ void store_chunk_s(char* stg, int tid,
                                              const uint4 r[4]) {
    int row = tid >> 1;
    int cb = (tid & 1) * 16;  // byte offset
#pragma unroll
    for (int t = 0; t < 4; t++)
        *(uint4*)(stg + t * TILE_BYTES + row * BSTR + cb) = r[t];
}

__device__ __forceinline__ void gemm_mma_body(
    const __nv_bfloat16* __restrict__ Ahi, const __nv_bfloat16* __restrict__ Alo,
    const __nv_bfloat16* __restrict__ Bhi, const __nv_bfloat16* __restrict__ Blo,
    float* __restrict__ C, bool rope) {
    extern __shared__ char smem[];
    int tid = threadIdx.x;
    int wid = tid >> 5;
    int lane = tid & 31;
    int m0 = blockIdx.y * GBM;
    int n0 = blockIdx.x * GBN;
    int warp_m = (wid & 3) * 32;
    int warp_n = (wid >> 2) * 64;

    int gidx = lane >> 2;          // groupID
    int ctg2 = (lane & 3) * 2;     // k element pair base

    float acc[2][8][4];
#pragma unroll
    for (int mi = 0; mi < 2; mi++)
#pragma unroll
        for (int nj = 0; nj < 8; nj++)
#pragma unroll
            for (int q = 0; q < 4; q++) acc[mi][nj][q] = 0.f;

    uint4 rbuf[4];
    load_chunk_g(Ahi, Alo, Bhi, Blo, m0, n0, 0, tid, rbuf);
    store_chunk_s(smem, tid, rbuf);
    __syncthreads();

    for (int c = 0; c < NCHUNK; c++) {
        if (c + 1 < NCHUNK)
            load_chunk_g(Ahi, Alo, Bhi, Blo, m0, n0, (c + 1) * GBK, tid, rbuf);

        char* st = smem + (c & 1) * STAGE_BYTES;
        const char* sa_hi = st;
        const char* sa_lo = st + TILE_BYTES;
        const char* sb_hi = st + 2 * TILE_BYTES;
        const char* sb_lo = st + 3 * TILE_BYTES;

        uint32_t ahi[2][4], alo[2][4];
#pragma unroll
        for (int mi = 0; mi < 2; mi++) {
            int r0 = (warp_m + mi * 16 + gidx) * BSTR;
            int klo = ctg2 * 2;
            int khi = (ctg2 + 8) * 2;
            ahi[mi][0] = *(const uint32_t*)(sa_hi + r0 + klo);
            ahi[mi][1] = *(const uint32_t*)(sa_hi + r0 + 8 * BSTR + klo);
            ahi[mi][2] = *(const uint32_t*)(sa_hi + r0 + khi);
            ahi[mi][3] = *(const uint32_t*)(sa_hi + r0 + 8 * BSTR + khi);
            alo[mi][0] = *(const uint32_t*)(sa_lo + r0 + klo);
            alo[mi][1] = *(const uint32_t*)(sa_lo + r0 + 8 * BSTR + klo);
            alo[mi][2] = *(const uint32_t*)(sa_lo + r0 + khi);
            alo[mi][3] = *(const uint32_t*)(sa_lo + r0 + 8 * BSTR + khi);
        }
#pragma unroll
        for (int nj = 0; nj < 8; nj++) {
            int rb = (warp_n + nj * 8 + gidx) * BSTR;
            uint32_t bhi[2], blo[2];
            bhi[0] = *(const uint32_t*)(sb_hi + rb + ctg2 * 2);
            bhi[1] = *(const uint32_t*)(sb_hi + rb + (ctg2 + 8) * 2);
            blo[0] = *(const uint32_t*)(sb_lo + rb + ctg2 * 2);
            blo[1] = *(const uint32_t*)(sb_lo + rb + (ctg2 + 8) * 2);
#pragma unroll
            for (int mi = 0; mi < 2; mi++) {
                mma_bf16(acc[mi][nj], ahi[mi], bhi);
                mma_bf16(acc[mi][nj], ahi[mi], blo);
                mma_bf16(acc[mi][nj], alo[mi], bhi);
            }
        }

        if (c + 1 < NCHUNK)
            store_chunk_s(smem + ((c + 1) & 1) * STAGE_BYTES, tid, rbuf);
        __syncthreads();
    }

    // epilogue (+ optional interleaved RoPE)
    int tig = lane & 3;
#pragma unroll
    for (int mi = 0; mi < 2; mi++) {
#pragma unroll
        for (int nj = 0; nj < 8; nj++) {
            int m = m0 + warp_m + mi * 16 + gidx;
            int n = n0 + warp_n + nj * 8 + tig * 2;
            float v0 = acc[mi][nj][0], v1 = acc[mi][nj][1];
            float v2 = acc[mi][nj][2], v3 = acc[mi][nj][3];
            if (rope) {
                int pi = (n & (HD - 1)) >> 1;
                int p0 = m & (SEQ - 1);
                int p8 = (m + 8) & (SEQ - 1);
                float c0 = g_cos[p0 * (HD / 2) + pi], s0 = g_sin[p0 * (HD / 2) + pi];
                float c8 = g_cos[p8 * (HD / 2) + pi], s8 = g_sin[p8 * (HD / 2) + pi];
                float t0 = v0 * c0 - v1 * s0, t1 = v0 * s0 + v1 * c0;
                float t2 = v2 * c8 - v3 * s8, t3 = v2 * s8 + v3 * c8;
                v0 = t0; v1 = t1; v2 = t2; v3 = t3;
            }
            *(float2*)&C[(size_t)m * E_DIM + n] = make_float2(v0, v1);
            *(float2*)&C[(size_t)(m + 8) * E_DIM + n] = make_float2(v2, v3);
        }
    }
}

__global__ __launch_bounds__(256, 2) void gemm_qkv_tc(void) {
    int z = blockIdx.z;
    const __nv_bfloat16* bh = g_w_hi + (size_t)z * E_DIM * E_DIM;
    const __nv_bfloat16* bl = g_w_lo + (size_t)z * E_DIM * E_DIM;
    float* C = (z == 0) ? g_q : (z == 1) ? g_k : g_v;
    gemm_mma_body(g_x_hi, g_x_lo, bh, bl, C, z < 2);
}

__global__ __launch_bounds__(256, 2) void gemm_out_tc(float* __restrict__ out) {
    const __nv_bfloat16* bh = g_w_hi + (size_t)3 * E_DIM * E_DIM;
    const __nv_bfloat16* bl = g_w_lo + (size_t)3 * E_DIM * E_DIM;
    gemm_mma_body(g_attn_hi, g_attn_lo, bh, bl, out, false);
}

// ---------------- Flash attention (fp32, causal) ---------------------------
#define FA_BM 64
#define FA_BN 64
#define QSTR 132
#define PSTR 65
#define FA_SMEM ((3 * FA_BM * QSTR + FA_BM * PSTR) * 4)

__global__ __launch_bounds__(256) void flash_kernel() {
    extern __shared__ float sm[];
    float* Qs = sm;
    float* Ks = Qs + FA_BM * QSTR;
    float* Vs = Ks + FA_BM * QSTR;
    float* Ps = Vs + FA_BM * QSTR;

    int qt = (gridDim.x - 1) - blockIdx.x;
    int bh = blockIdx.y;
    int b = bh >> 4;
    int h = bh & 15;
    int tid = threadIdx.x;
    int qr = tid >> 2;
    int dg = tid & 3;

    const float* qbase = g_q + (size_t)b * SEQ * E_DIM + (size_t)h * HD;
    const float* kbase = g_k + (size_t)b * SEQ * E_DIM + (size_t)h * HD;
    const float* vbase = g_v + (size_t)b * SEQ * E_DIM + (size_t)h * HD;

#pragma unroll
    for (int it = 0; it < 8; it++) {
        int l = tid + it * 256;
        int row = l >> 5;
        int c4 = (l & 31) * 4;
        *(float4*)&Qs[row * QSTR + c4] =
            *(const float4*)&qbase[(size_t)(qt * FA_BM + row) * E_DIM + c4];
    }

    float acc[32];
#pragma unroll
    for (int d = 0; d < 32; d++) acc[d] = 0.f;
    float m_i = -1e30f, l_i = 0.f;
    const float scale = 0.08838834764831845f;
    int qg = qt * FA_BM + qr;

    for (int kt = 0; kt <= qt; kt++) {
        __syncthreads();
#pragma unroll
        for (int it = 0; it < 8; it++) {
            int l = tid + it * 256;
            int row = l >> 5;
            int c4 = (l & 31) * 4;
            *(float4*)&Ks[row * QSTR + c4] =
                *(const float4*)&kbase[(size_t)(kt * FA_BN + row) * E_DIM + c4];
            *(float4*)&Vs[row * QSTR + c4] =
                *(const float4*)&vbase[(size_t)(kt * FA_BN + row) * E_DIM + c4];
        }
        __syncthreads();

        float sreg[16];
#pragma unroll
        for (int jj = 0; jj < 16; jj++) sreg[jj] = 0.f;
        for (int d4 = 0; d4 < HD; d4 += 4) {
            float4 qv = *(float4*)&Qs[qr * QSTR + d4];
#pragma unroll
            for (int jj = 0; jj < 16; jj++) {
                int j = jj * 4 + dg;
                float4 kv = *(float4*)&Ks[j * QSTR + d4];
                sreg[jj] += qv.x * kv.x + qv.y * kv.y + qv.z * kv.z + qv.w * kv.w;
            }
        }

        float mtile = -1e30f;
#pragma unroll
        for (int jj = 0; jj < 16; jj++) {
            int kg = kt * FA_BN + jj * 4 + dg;
            float sv = sreg[jj] * scale;
            sv = (kg <= qg) ? sv : -1e30f;
            sreg[jj] = sv;
            mtile = fmaxf(mtile, sv);
        }
        mtile = fmaxf(mtile, __shfl_xor_sync(0xffffffffu, mtile, 1));
        mtile = fmaxf(mtile, __shfl_xor_sync(0xffffffffu, mtile, 2));
        float m_new = fmaxf(m_i, mtile);

        float lsum = 0.f;
#pragma unroll
        for (int jj = 0; jj < 16; jj++) {
            float p = __expf(sreg[jj] - m_new);
            sreg[jj] = p;
            lsum += p;
        }
        lsum += __shfl_xor_sync(0xffffffffu, lsum, 1);
        lsum += __shfl_xor_sync(0xffffffffu, lsum, 2);

        float alpha = __expf(m_i - m_new);
        m_i = m_new;
        l_i = l_i * alpha + lsum;
#pragma unroll
        for (int d = 0; d < 32; d++) acc[d] *= alpha;

#pragma unroll
        for (int jj = 0; jj < 16; jj++) Ps[qr * PSTR + jj * 4 + dg] = sreg[jj];
        __syncwarp();

#pragma unroll 4
        for (int j = 0; j < FA_BN; j++) {
            float p = Ps[qr * PSTR + j];
            const float4* vrow = (const float4*)&Vs[j * QSTR + dg * 32];
#pragma unroll
            for (int d4 = 0; d4 < 8; d4++) {
                float4 vv = vrow[d4];
                acc[d4 * 4 + 0] += p * vv.x;
                acc[d4 * 4 + 1] += p * vv.y;
                acc[d4 * 4 + 2] += p * vv.z;
                acc[d4 * 4 + 3] += p * vv.w;
            }
        }
        __syncwarp();
    }

    float inv_l = 1.0f / l_i;
    size_t obase = (size_t)b * SEQ * E_DIM + (size_t)(qt * FA_BM + qr) * E_DIM +
                   (size_t)h * HD + dg * 32;
#pragma unroll
    for (int d4 = 0; d4 < 8; d4++) {
        float o0 = acc[d4 * 4 + 0] * inv_l;
        float o1 = acc[d4 * 4 + 1] * inv_l;
        float o2 = acc[d4 * 4 + 2] * inv_l;
        float o3 = acc[d4 * 4 + 3] * inv_l;
        __nv_bfloat16 h0 = __float2bfloat16(o0);
        __nv_bfloat16 h1 = __float2bfloat16(o1);
        __nv_bfloat16 h2 = __float2bfloat16(o2);
        __nv_bfloat16 h3 = __float2bfloat16(o3);
        *(__nv_bfloat162*)&g_attn_hi[obase + d4 * 4 + 0] = __nv_bfloat162(h0, h1);
        *(__nv_bfloat162*)&g_attn_hi[obase + d4 * 4 + 2] = __nv_bfloat162(h2, h3);
        *(__nv_bfloat162*)&g_attn_lo[obase + d4 * 4 + 0] =
            __nv_bfloat162(__float2bfloat16(o0 - __bfloat162float(h0)),
                           __float2bfloat16(o1 - __bfloat162float(h1)));
        *(__nv_bfloat162*)&g_attn_lo[obase + d4 * 4 + 2] =
            __nv_bfloat162(__float2bfloat16(o2 - __bfloat162float(h2)),
                           __float2bfloat16(o3 - __bfloat162float(h3)));
    }
}

// ---------------- launcher ---------------------------------------------------
extern "C" void kernel_launch(void* const* d_in, const int* in_sizes, int n_in,
                              void* d_out, int out_size) {
    const float* x = (const float*)d_in[0];
    const float* Wq = (const float*)d_in[1];
    const float* Wk = (const float*)d_in[2];
    const float* Wv = (const float*)d_in[3];
    const float* Wo = (const float*)d_in[4];
    float* out = (float*)d_out;

    cudaFuncSetAttribute(flash_kernel, cudaFuncAttributeMaxDynamicSharedMemorySize,
                         FA_SMEM);
    cudaFuncSetAttribute(gemm_qkv_tc, cudaFuncAttributeMaxDynamicSharedMemorySize,
                         GEMM_SMEM);
    cudaFuncSetAttribute(gemm_out_tc, cudaFuncAttributeMaxDynamicSharedMemorySize,
                         GEMM_SMEM);

    rope_init_kernel<<<(SEQ * (HD / 2) + 255) / 256, 256>>>();

    {
        int n4 = MROWS * E_DIM / 4;
        convert_x_kernel<<<(n4 + 255) / 256, 256>>>((const float4*)x);
        int w4 = E_DIM * E_DIM / 4;
        convert_w_kernel<<<(w4 + 255) / 256, 256>>>((const float4*)Wq, 0);
        convert_w_kernel<<<(w4 + 255) / 256, 256>>>((const float4*)Wk, 1);
        convert_w_kernel<<<(w4 + 255) / 256, 256>>>((const float4*)Wv, 2);
        convert_w_kernel<<<(w4 + 255) / 256, 256>>>((const float4*)Wo, 3);
    }

    dim3 gqkv(E_DIM / GBN, MROWS / GBM, 3);
    gemm_qkv_tc<<<gqkv, 256, GEMM_SMEM>>>();

    dim3 gfa(SEQ / FA_BM, NBATCH * NHEAD);
    flash_kernel<<<gfa, 256, FA_SMEM>>>();

    dim3 gout(E_DIM / GBN, MROWS / GBM);
    gemm_out_tc<<<gout, 256, GEMM_SMEM>>>(out);
}

// round 6
// speedup vs baseline: 4.1700x; 3.4340x over previous
#include <cuda_runtime.h>
#include <cuda_bf16.h>
#include <math.h>
#include <stdint.h>

#define E_DIM 2048
#define SEQ 2048
#define NBATCH 2
#define NHEAD 16
#define HD 128
#define MROWS (NBATCH * SEQ) /* 4096 */

// ---------------- scratch (device globals; no allocation allowed) ----------
__device__ __nv_bfloat16 g_x_hi[MROWS * E_DIM];
__device__ __nv_bfloat16 g_x_lo[MROWS * E_DIM];
__device__ __nv_bfloat16 g_w_hi[4 * E_DIM * E_DIM];
__device__ __nv_bfloat16 g_w_lo[4 * E_DIM * E_DIM];
// head-contiguous [bh][s][d] bf16 hi/lo
__device__ __nv_bfloat16 g_qhi[MROWS * E_DIM];
__device__ __nv_bfloat16 g_qlo[MROWS * E_DIM];
__device__ __nv_bfloat16 g_khi[MROWS * E_DIM];
__device__ __nv_bfloat16 g_klo[MROWS * E_DIM];
__device__ __nv_bfloat16 g_vhi[MROWS * E_DIM];
__device__ __nv_bfloat16 g_vlo[MROWS * E_DIM];
// transposed V: [bh][d][s]
__device__ __nv_bfloat16 g_vthi[MROWS * E_DIM];
__device__ __nv_bfloat16 g_vtlo[MROWS * E_DIM];
__device__ __nv_bfloat16 g_attn_hi[MROWS * E_DIM];
__device__ __nv_bfloat16 g_attn_lo[MROWS * E_DIM];
__device__ float g_cos[SEQ * (HD / 2)];
__device__ float g_sin[SEQ * (HD / 2)];

// ---------------- helpers ----------------------------------------------------
__device__ __forceinline__ void mma_bf16(float* d, const uint32_t* a,
                                         const uint32_t* b) {
    asm volatile(
        "mma.sync.aligned.m16n8k16.row.col.f32.bf16.bf16.f32 "
        "{%0,%1,%2,%3}, {%4,%5,%6,%7}, {%8,%9}, {%0,%1,%2,%3};"
        : "+f"(d[0]), "+f"(d[1]), "+f"(d[2]), "+f"(d[3])
        : "r"(a[0]), "r"(a[1]), "r"(a[2]), "r"(a[3]), "r"(b[0]), "r"(b[1]));
}

__device__ __forceinline__ void split_pack(float x, float y, uint32_t& hi,
                                           uint32_t& lo) {
    __nv_bfloat16 hx = __float2bfloat16(x), hy = __float2bfloat16(y);
    __nv_bfloat162 h2(hx, hy);
    hi = *(uint32_t*)&h2;
    __nv_bfloat162 l2(__float2bfloat16(x - __bfloat162float(hx)),
                      __float2bfloat16(y - __bfloat162float(hy)));
    lo = *(uint32_t*)&l2;
}

__device__ __forceinline__ void split_store2(__nv_bfloat16* hi,
                                             __nv_bfloat16* lo, size_t idx,
                                             float x, float y) {
    uint32_t h, l;
    split_pack(x, y, h, l);
    *(uint32_t*)(hi + idx) = h;
    *(uint32_t*)(lo + idx) = l;
}

// ---------------- RoPE table ------------------------------------------------
__global__ void rope_init_kernel() {
    int idx = blockIdx.x * blockDim.x + threadIdx.x;
    if (idx >= SEQ * (HD / 2)) return;
    int pos = idx / (HD / 2);
    int i = idx % (HD / 2);
    double invd = pow(10000.0, -(double)(2 * i) / (double)HD);
    float inv = (float)invd;
    float ang = (float)pos * inv;
    g_cos[idx] = (float)cos((double)ang);
    g_sin[idx] = (float)sin((double)ang);
}

// ---------------- fp32 -> split bf16 conversion -----------------------------
__device__ __forceinline__ void split_store4(__nv_bfloat162* hi,
                                             __nv_bfloat162* lo, int i,
                                             float4 v) {
    __nv_bfloat16 h0 = __float2bfloat16(v.x);
    __nv_bfloat16 h1 = __float2bfloat16(v.y);
    __nv_bfloat16 h2 = __float2bfloat16(v.z);
    __nv_bfloat16 h3 = __float2bfloat16(v.w);
    hi[i * 2 + 0] = __nv_bfloat162(h0, h1);
    hi[i * 2 + 1] = __nv_bfloat162(h2, h3);
    lo[i * 2 + 0] = __nv_bfloat162(__float2bfloat16(v.x - __bfloat162float(h0)),
                                   __float2bfloat16(v.y - __bfloat162float(h1)));
    lo[i * 2 + 1] = __nv_bfloat162(__float2bfloat16(v.z - __bfloat162float(h2)),
                                   __float2bfloat16(v.w - __bfloat162float(h3)));
}

__global__ void convert_x_kernel(const float4* __restrict__ src) {
    int i = blockIdx.x * blockDim.x + threadIdx.x;
    if (i >= MROWS * E_DIM / 4) return;
    split_store4((__nv_bfloat162*)g_x_hi, (__nv_bfloat162*)g_x_lo, i, src[i]);
}

__global__ void convert_w_kernel(const float4* __restrict__ src, int z) {
    int i = blockIdx.x * blockDim.x + threadIdx.x;
    if (i >= E_DIM * E_DIM / 4) return;
    split_store4((__nv_bfloat162*)(g_w_hi + (size_t)z * E_DIM * E_DIM),
                 (__nv_bfloat162*)(g_w_lo + (size_t)z * E_DIM * E_DIM), i, src[i]);
}

// ---------------- HMMA GEMM: C[m,n] = sum_k A[m,k]*B[n,k] -------------------
#define GBM 128
#define GBN 128
#define GBK 16
#define NCHUNK (E_DIM / GBK) /* 128 */
#define BSTR 48
#define TILE_BYTES (128 * BSTR)
#define STAGE_BYTES (4 * TILE_BYTES)
#define GEMM_SMEM (2 * STAGE_BYTES)

__device__ __forceinline__ void load_chunk_g(
    const __nv_bfloat16* __restrict__ Ahi, const __nv_bfloat16* __restrict__ Alo,
    const __nv_bfloat16* __restrict__ Bhi, const __nv_bfloat16* __restrict__ Blo,
    int m0, int n0, int k0, int tid, uint4 r[4]) {
    int row = tid >> 1;
    int ce = (tid & 1) * 8;
    r[0] = *(const uint4*)(Ahi + (size_t)(m0 + row) * E_DIM + k0 + ce);
    r[1] = *(const uint4*)(Alo + (size_t)(m0 + row) * E_DIM + k0 + ce);
    r[2] = *(const uint4*)(Bhi + (size_t)(n0 + row) * E_DIM + k0 + ce);
    r[3] = *(const uint4*)(Blo + (size_t)(n0 + row) * E_DIM + k0 + ce);
}

__device__ __forceinline__ void store_chunk_s(char* stg, int tid,
                                              const uint4 r[4]) {
    int row = tid >> 1;
    int cb = (tid & 1) * 16;
#pragma unroll
    for (int t = 0; t < 4; t++)
        *(uint4*)(stg + t * TILE_BYTES + row * BSTR + cb) = r[t];
}

// mode: 0=Q (rope+scale, split->g_q*), 1=K (rope, ->g_k*), 2=V (->g_v*), 3=fp32 out
__device__ __forceinline__ void gemm_mma_body(
    const __nv_bfloat16* __restrict__ Ahi, const __nv_bfloat16* __restrict__ Alo,
    const __nv_bfloat16* __restrict__ Bhi, const __nv_bfloat16* __restrict__ Blo,
    float* __restrict__ Cout, int mode) {
    extern __shared__ char smem[];
    int tid = threadIdx.x;
    int wid = tid >> 5;
    int lane = tid & 31;
    int m0 = blockIdx.y * GBM;
    int n0 = blockIdx.x * GBN;
    int warp_m = (wid & 3) * 32;
    int warp_n = (wid >> 2) * 64;

    int gidx = lane >> 2;
    int ctg2 = (lane & 3) * 2;

    float acc[2][8][4];
#pragma unroll
    for (int mi = 0; mi < 2; mi++)
#pragma unroll
        for (int nj = 0; nj < 8; nj++)
#pragma unroll
            for (int q = 0; q < 4; q++) acc[mi][nj][q] = 0.f;

    uint4 rbuf[4];
    load_chunk_g(Ahi, Alo, Bhi, Blo, m0, n0, 0, tid, rbuf);
    store_chunk_s(smem, tid, rbuf);
    __syncthreads();

    for (int c = 0; c < NCHUNK; c++) {
        if (c + 1 < NCHUNK)
            load_chunk_g(Ahi, Alo, Bhi, Blo, m0, n0, (c + 1) * GBK, tid, rbuf);

        char* st = smem + (c & 1) * STAGE_BYTES;
        const char* sa_hi = st;
        const char* sa_lo = st + TILE_BYTES;
        const char* sb_hi = st + 2 * TILE_BYTES;
        const char* sb_lo = st + 3 * TILE_BYTES;

        uint32_t ahi[2][4], alo[2][4];
#pragma unroll
        for (int mi = 0; mi < 2; mi++) {
            int r0 = (warp_m + mi * 16 + gidx) * BSTR;
            int klo = ctg2 * 2;
            int khi = (ctg2 + 8) * 2;
            ahi[mi][0] = *(const uint32_t*)(sa_hi + r0 + klo);
            ahi[mi][1] = *(const uint32_t*)(sa_hi + r0 + 8 * BSTR + klo);
            ahi[mi][2] = *(const uint32_t*)(sa_hi + r0 + khi);
            ahi[mi][3] = *(const uint32_t*)(sa_hi + r0 + 8 * BSTR + khi);
            alo[mi][0] = *(const uint32_t*)(sa_lo + r0 + klo);
            alo[mi][1] = *(const uint32_t*)(sa_lo + r0 + 8 * BSTR + klo);
            alo[mi][2] = *(const uint32_t*)(sa_lo + r0 + khi);
            alo[mi][3] = *(const uint32_t*)(sa_lo + r0 + 8 * BSTR + khi);
        }
#pragma unroll
        for (int nj = 0; nj < 8; nj++) {
            int rb = (warp_n + nj * 8 + gidx) * BSTR;
            uint32_t bhi[2], blo[2];
            bhi[0] = *(const uint32_t*)(sb_hi + rb + ctg2 * 2);
            bhi[1] = *(const uint32_t*)(sb_hi + rb + (ctg2 + 8) * 2);
            blo[0] = *(const uint32_t*)(sb_lo + rb + ctg2 * 2);
            blo[1] = *(const uint32_t*)(sb_lo + rb + (ctg2 + 8) * 2);
#pragma unroll
            for (int mi = 0; mi < 2; mi++) {
                mma_bf16(acc[mi][nj], ahi[mi], bhi);
                mma_bf16(acc[mi][nj], ahi[mi], blo);
                mma_bf16(acc[mi][nj], alo[mi], bhi);
            }
        }

        if (c + 1 < NCHUNK)
            store_chunk_s(smem + ((c + 1) & 1) * STAGE_BYTES, tid, rbuf);
        __syncthreads();
    }

    int tig = lane & 3;
    __nv_bfloat16* dhi = (mode == 0) ? g_qhi : (mode == 1) ? g_khi : g_vhi;
    __nv_bfloat16* dlo = (mode == 0) ? g_qlo : (mode == 1) ? g_klo : g_vlo;
    const float qsc = (mode == 0) ? 0.08838834764831845f : 1.0f;

#pragma unroll
    for (int mi = 0; mi < 2; mi++) {
#pragma unroll
        for (int nj = 0; nj < 8; nj++) {
            int m = m0 + warp_m + mi * 16 + gidx;
            int n = n0 + warp_n + nj * 8 + tig * 2;
            float v0 = acc[mi][nj][0], v1 = acc[mi][nj][1];
            float v2 = acc[mi][nj][2], v3 = acc[mi][nj][3];
            if (mode <= 1) {
                int pi = (n & (HD - 1)) >> 1;
                int p0 = m & (SEQ - 1);
                int p8 = p0 + 8;
                float c0 = g_cos[p0 * (HD / 2) + pi], s0 = g_sin[p0 * (HD / 2) + pi];
                float c8 = g_cos[p8 * (HD / 2) + pi], s8 = g_sin[p8 * (HD / 2) + pi];
                float t0 = v0 * c0 - v1 * s0, t1 = v0 * s0 + v1 * c0;
                float t2 = v2 * c8 - v3 * s8, t3 = v2 * s8 + v3 * c8;
                v0 = t0 * qsc; v1 = t1 * qsc; v2 = t2 * qsc; v3 = t3 * qsc;
            }
            if (mode == 3) {
                *(float2*)&Cout[(size_t)m * E_DIM + n] = make_float2(v0, v1);
                *(float2*)&Cout[(size_t)(m + 8) * E_DIM + n] = make_float2(v2, v3);
            } else {
                int b = m >> 11, s = m & 2047, h = n >> 7, d = n & 127;
                size_t base0 = ((size_t)(b * NHEAD + h) * SEQ + s) * HD + d;
                size_t base1 = base0 + 8 * HD;
                split_store2(dhi, dlo, base0, v0, v1);
                split_store2(dhi, dlo, base1, v2, v3);
            }
        }
    }
}

__global__ __launch_bounds__(256, 2) void gemm_qkv_tc(void) {
    int z = blockIdx.z;
    const __nv_bfloat16* bh = g_w_hi + (size_t)z * E_DIM * E_DIM;
    const __nv_bfloat16* bl = g_w_lo + (size_t)z * E_DIM * E_DIM;
    gemm_mma_body(g_x_hi, g_x_lo, bh, bl, nullptr, z);
}

__global__ __launch_bounds__(256, 2) void gemm_out_tc(float* __restrict__ out) {
    const __nv_bfloat16* bh = g_w_hi + (size_t)3 * E_DIM * E_DIM;
    const __nv_bfloat16* bl = g_w_lo + (size_t)3 * E_DIM * E_DIM;
    gemm_mma_body(g_attn_hi, g_attn_lo, bh, bl, out, 3);
}

// ---------------- V transpose: [bh][s][d] -> [bh][d][s] ---------------------
__global__ void transpose_v_kernel() {
    __shared__ __nv_bfloat16 t[32][33];
    int bh = blockIdx.z >> 1;
    const __nv_bfloat16* src = (blockIdx.z & 1) ? g_vlo : g_vhi;
    __nv_bfloat16* dst = (blockIdx.z & 1) ? g_vtlo : g_vthi;
    int tx = threadIdx.x, ty = threadIdx.y;
    int s0 = blockIdx.x * 32, d0 = blockIdx.y * 32;
#pragma unroll
    for (int i = 0; i < 32; i += 8)
        t[ty + i][tx] = src[((size_t)bh * SEQ + s0 + ty + i) * HD + d0 + tx];
    __syncthreads();
#pragma unroll
    for (int i = 0; i < 32; i += 8)
        dst[((size_t)bh * HD + d0 + ty + i) * SEQ + s0 + tx] = t[tx][ty + i];
}

// ---------------- Tensor-core flash attention (causal) ----------------------
// 4 warps, 64x64 tiles, D=128. Q frags in regs; K/Vt in smem; 3x bf16 split.
#define KSTR_B 272  /* K row stride bytes (128 bf16 + pad) */
#define VSTR_B 144  /* Vt row stride bytes (64 bf16 + pad) */
#define SM_KHI 0
#define SM_KLO (64 * KSTR_B)
#define SM_VHI (2 * 64 * KSTR_B)
#define SM_VLO (SM_VHI + 128 * VSTR_B)
#define FLASH_SMEM (SM_VLO + 128 * VSTR_B) /* 71680 */

__global__ __launch_bounds__(128) void flash_mma_kernel() {
    extern __shared__ char sm[];
    char* skhi = sm + SM_KHI;
    char* sklo = sm + SM_KLO;
    char* svhi = sm + SM_VHI;
    char* svlo = sm + SM_VLO;

    int tid = threadIdx.x;
    int wid = tid >> 5;
    int lane = tid & 31;
    int qt = (int)gridDim.x - 1 - (int)blockIdx.x;  // heavy tiles first
    int bh = blockIdx.y;
    int g = lane >> 2;
    int c = lane & 3;
    int warp_m = wid * 16;

    // ---- Q fragments (registers, loaded once from global) ----
    uint32_t qh[8][4], ql[8][4];
    {
        const __nv_bfloat16* Qh = g_qhi + (size_t)bh * SEQ * HD + (size_t)qt * 64 * HD;
        const __nv_bfloat16* Ql = g_qlo + (size_t)bh * SEQ * HD + (size_t)qt * 64 * HD;
        int r0 = (warp_m + g) * HD, r1 = (warp_m + g + 8) * HD;
#pragma unroll
        for (int kc = 0; kc < 8; kc++) {
            int c0 = kc * 16 + c * 2, c1 = c0 + 8;
            qh[kc][0] = *(const uint32_t*)(Qh + r0 + c0);
            qh[kc][1] = *(const uint32_t*)(Qh + r1 + c0);
            qh[kc][2] = *(const uint32_t*)(Qh + r0 + c1);
            qh[kc][3] = *(const uint32_t*)(Qh + r1 + c1);
            ql[kc][0] = *(const uint32_t*)(Ql + r0 + c0);
            ql[kc][1] = *(const uint32_t*)(Ql + r1 + c0);
            ql[kc][2] = *(const uint32_t*)(Ql + r0 + c1);
            ql[kc][3] = *(const uint32_t*)(Ql + r1 + c1);
        }
    }

    float o[16][4];
#pragma unroll
    for (int t = 0; t < 16; t++)
#pragma unroll
        for (int q = 0; q < 4; q++) o[t][q] = 0.f;
    float m0 = -1e30f, m1 = -1e30f, l0 = 0.f, l1 = 0.f;

    const __nv_bfloat16* Kh = g_khi + (size_t)bh * SEQ * HD;
    const __nv_bfloat16* Kl = g_klo + (size_t)bh * SEQ * HD;
    const __nv_bfloat16* Vh = g_vthi + (size_t)bh * HD * SEQ;
    const __nv_bfloat16* Vl = g_vtlo + (size_t)bh * HD * SEQ;

    for (int kt = 0; kt <= qt; kt++) {
        __syncthreads();
        {
            const uint4* srch = (const uint4*)(Kh + (size_t)kt * 64 * HD);
            const uint4* srcl = (const uint4*)(Kl + (size_t)kt * 64 * HD);
#pragma unroll
            for (int i = 0; i < 8; i++) {
                int idx = tid + i * 128;
                int row = idx >> 4, cc = idx & 15;
                *(uint4*)(skhi + row * KSTR_B + cc * 16) = srch[idx];
                *(uint4*)(sklo + row * KSTR_B + cc * 16) = srcl[idx];
            }
#pragma unroll
            for (int i = 0; i < 8; i++) {
                int idx = tid + i * 128;
                int row = idx >> 3, cc = idx & 7;
                const uint4* vrh = (const uint4*)(Vh + (size_t)row * SEQ + kt * 64);
                const uint4* vrl = (const uint4*)(Vl + (size_t)row * SEQ + kt * 64);
                *(uint4*)(svhi + row * VSTR_B + cc * 16) = vrh[cc];
                *(uint4*)(svlo + row * VSTR_B + cc * 16) = vrl[cc];
            }
        }
        __syncthreads();

        // ---- S = Q @ K^T (64x64 per CTA, 16x64 per warp) ----
        float s_acc[8][4];
#pragma unroll
        for (int nj = 0; nj < 8; nj++)
#pragma unroll
            for (int q = 0; q < 4; q++) s_acc[nj][q] = 0.f;

#pragma unroll
        for (int kc = 0; kc < 8; kc++) {
#pragma unroll
            for (int nj = 0; nj < 8; nj++) {
                int off = (nj * 8 + g) * KSTR_B + kc * 32 + c * 4;
                uint32_t bh2[2], bl2[2];
                bh2[0] = *(const uint32_t*)(skhi + off);
                bh2[1] = *(const uint32_t*)(skhi + off + 16);
                bl2[0] = *(const uint32_t*)(sklo + off);
                bl2[1] = *(const uint32_t*)(sklo + off + 16);
                mma_bf16(s_acc[nj], qh[kc], bh2);
                mma_bf16(s_acc[nj], qh[kc], bl2);
                mma_bf16(s_acc[nj], ql[kc], bh2);
            }
        }

        // ---- causal mask (diagonal tile only) ----
        if (kt == qt) {
            int row0 = warp_m + g, row1 = row0 + 8;
#pragma unroll
            for (int nj = 0; nj < 8; nj++) {
                int col = nj * 8 + c * 2;
                if (col > row0) s_acc[nj][0] = -1e30f;
                if (col + 1 > row0) s_acc[nj][1] = -1e30f;
                if (col > row1) s_acc[nj][2] = -1e30f;
                if (col + 1 > row1) s_acc[nj][3] = -1e30f;
            }
        }

        // ---- online softmax ----
        float mt0 = -1e30f, mt1 = -1e30f;
#pragma unroll
        for (int nj = 0; nj < 8; nj++) {
            mt0 = fmaxf(mt0, fmaxf(s_acc[nj][0], s_acc[nj][1]));
            mt1 = fmaxf(mt1, fmaxf(s_acc[nj][2], s_acc[nj][3]));
        }
        mt0 = fmaxf(mt0, __shfl_xor_sync(0xffffffffu, mt0, 1));
        mt0 = fmaxf(mt0, __shfl_xor_sync(0xffffffffu, mt0, 2));
        mt1 = fmaxf(mt1, __shfl_xor_sync(0xffffffffu, mt1, 1));
        mt1 = fmaxf(mt1, __shfl_xor_sync(0xffffffffu, mt1, 2));
        float mn0 = fmaxf(m0, mt0), mn1 = fmaxf(m1, mt1);
        float a0 = __expf(m0 - mn0), a1 = __expf(m1 - mn1);
        m0 = mn0; m1 = mn1;
#pragma unroll
        for (int t = 0; t < 16; t++) {
            o[t][0] *= a0; o[t][1] *= a0;
            o[t][2] *= a1; o[t][3] *= a1;
        }
        float rs0 = 0.f, rs1 = 0.f;
#pragma unroll
        for (int nj = 0; nj < 8; nj++) {
            float p0 = __expf(s_acc[nj][0] - mn0);
            float p1 = __expf(s_acc[nj][1] - mn0);
            float p2 = __expf(s_acc[nj][2] - mn1);
            float p3 = __expf(s_acc[nj][3] - mn1);
            s_acc[nj][0] = p0; s_acc[nj][1] = p1;
            s_acc[nj][2] = p2; s_acc[nj][3] = p3;
            rs0 += p0 + p1; rs1 += p2 + p3;
        }
        l0 = l0 * a0 + rs0;  // per-lane partial; reduced at end
        l1 = l1 * a1 + rs1;

        // ---- P fragments (in registers; C-layout == A-layout) ----
        uint32_t ph[4][4], pl[4][4];
#pragma unroll
        for (int kc = 0; kc < 4; kc++) {
            split_pack(s_acc[2 * kc][0], s_acc[2 * kc][1], ph[kc][0], pl[kc][0]);
            split_pack(s_acc[2 * kc][2], s_acc[2 * kc][3], ph[kc][1], pl[kc][1]);
            split_pack(s_acc[2 * kc + 1][0], s_acc[2 * kc + 1][1], ph[kc][2], pl[kc][2]);
            split_pack(s_acc[2 * kc + 1][2], s_acc[2 * kc + 1][3], ph[kc][3], pl[kc][3]);
        }

        // ---- O += P @ V ----
#pragma unroll
        for (int nj = 0; nj < 16; nj++) {
#pragma unroll
            for (int kc = 0; kc < 4; kc++) {
                int off = (nj * 8 + g) * VSTR_B + kc * 32 + c * 4;
                uint32_t vh2[2], vl2[2];
                vh2[0] = *(const uint32_t*)(svhi + off);
                vh2[1] = *(const uint32_t*)(svhi + off + 16);
                vl2[0] = *(const uint32_t*)(svlo + off);
                vl2[1] = *(const uint32_t*)(svlo + off + 16);
                mma_bf16(o[nj], ph[kc], vh2);
                mma_bf16(o[nj], ph[kc], vl2);
                mma_bf16(o[nj], pl[kc], vh2);
            }
        }
    }

    // ---- finalize ----
    l0 += __shfl_xor_sync(0xffffffffu, l0, 1);
    l0 += __shfl_xor_sync(0xffffffffu, l0, 2);
    l1 += __shfl_xor_sync(0xffffffffu, l1, 1);
    l1 += __shfl_xor_sync(0xffffffffu, l1, 2);
    float i0 = 1.0f / l0, i1 = 1.0f / l1;
    int b = bh >> 4, h = bh & 15;
    int s0 = qt * 64 + warp_m + g;
    size_t r0 = ((size_t)b * SEQ + s0) * E_DIM + h * HD;
    size_t r1 = ((size_t)b * SEQ + s0 + 8) * E_DIM + h * HD;
#pragma unroll
    for (int nj = 0; nj < 16; nj++) {
        int d = nj * 8 + c * 2;
        split_store2(g_attn_hi, g_attn_lo, r0 + d, o[nj][0] * i0, o[nj][1] * i0);
        split_store2(g_attn_hi, g_attn_lo, r1 + d, o[nj][2] * i1, o[nj][3] * i1);
    }
}

// ---------------- launcher ---------------------------------------------------
extern "C" void kernel_launch(void* const* d_in, const int* in_sizes, int n_in,
                              void* d_out, int out_size) {
    const float* x = (const float*)d_in[0];
    const float* Wq = (const float*)d_in[1];
    const float* Wk = (const float*)d_in[2];
    const float* Wv = (const float*)d_in[3];
    const float* Wo = (const float*)d_in[4];
    float* out = (float*)d_out;

    cudaFuncSetAttribute(gemm_qkv_tc, cudaFuncAttributeMaxDynamicSharedMemorySize,
                         GEMM_SMEM);
    cudaFuncSetAttribute(gemm_out_tc, cudaFuncAttributeMaxDynamicSharedMemorySize,
                         GEMM_SMEM);
    cudaFuncSetAttribute(flash_mma_kernel,
                         cudaFuncAttributeMaxDynamicSharedMemorySize, FLASH_SMEM);

    rope_init_kernel<<<(SEQ * (HD / 2) + 255) / 256, 256>>>();

    {
        int n4 = MROWS * E_DIM / 4;
        convert_x_kernel<<<(n4 + 255) / 256, 256>>>((const float4*)x);
        int w4 = E_DIM * E_DIM / 4;
        convert_w_kernel<<<(w4 + 255) / 256, 256>>>((const float4*)Wq, 0);
        convert_w_kernel<<<(w4 + 255) / 256, 256>>>((const float4*)Wk, 1);
        convert_w_kernel<<<(w4 + 255) / 256, 256>>>((const float4*)Wv, 2);
        convert_w_kernel<<<(w4 + 255) / 256, 256>>>((const float4*)Wo, 3);
    }

    dim3 gqkv(E_DIM / GBN, MROWS / GBM, 3);
    gemm_qkv_tc<<<gqkv, 256, GEMM_SMEM>>>();

    dim3 gtr(SEQ / 32, HD / 32, NBATCH * NHEAD * 2);
    transpose_v_kernel<<<gtr, dim3(32, 8)>>>();

    dim3 gfa(SEQ / 64, NBATCH * NHEAD);
    flash_mma_kernel<<<gfa, 128, FLASH_SMEM>>>();

    dim3 gout(E_DIM / GBN, MROWS / GBM);
    gemm_out_tc<<<gout, 256, GEMM_SMEM>>>(out);
}

// round 7
// speedup vs baseline: 4.6647x; 1.1186x over previous
#include <cuda_runtime.h>
#include <cuda_bf16.h>
#include <math.h>
#include <stdint.h>

#define E_DIM 2048
#define SEQ 2048
#define NBATCH 2
#define NHEAD 16
#define HD 128
#define MROWS (NBATCH * SEQ) /* 4096 */

// ---------------- scratch (device globals; no allocation allowed) ----------
__device__ __nv_bfloat16 g_x_hi[MROWS * E_DIM];
__device__ __nv_bfloat16 g_x_lo[MROWS * E_DIM];
__device__ __nv_bfloat16 g_w_hi[4 * E_DIM * E_DIM];
__device__ __nv_bfloat16 g_w_lo[4 * E_DIM * E_DIM];
__device__ __nv_bfloat16 g_qhi[MROWS * E_DIM];
__device__ __nv_bfloat16 g_qlo[MROWS * E_DIM];
__device__ __nv_bfloat16 g_khi[MROWS * E_DIM];
__device__ __nv_bfloat16 g_klo[MROWS * E_DIM];
__device__ __nv_bfloat16 g_vhi[MROWS * E_DIM];
__device__ __nv_bfloat16 g_vlo[MROWS * E_DIM];
__device__ __nv_bfloat16 g_vthi[MROWS * E_DIM];
__device__ __nv_bfloat16 g_vtlo[MROWS * E_DIM];
__device__ __nv_bfloat16 g_attn_hi[MROWS * E_DIM];
__device__ __nv_bfloat16 g_attn_lo[MROWS * E_DIM];
__device__ float g_cos[SEQ * (HD / 2)];
__device__ float g_sin[SEQ * (HD / 2)];

// ---------------- helpers ----------------------------------------------------
__device__ __forceinline__ uint32_t smem_u32(const void* p) {
    uint32_t a;
    asm("{ .reg .u64 t; cvta.to.shared.u64 t, %1; cvt.u32.u64 %0, t; }"
        : "=r"(a) : "l"(p));
    return a;
}
__device__ __forceinline__ void cp_async16(uint32_t dst, const void* src) {
    asm volatile("cp.async.cg.shared.global [%0], [%1], 16;"
                 :: "r"(dst), "l"(src));
}
#define CP_COMMIT() asm volatile("cp.async.commit_group;" ::: "memory")
#define CP_WAIT2() asm volatile("cp.async.wait_group 2;" ::: "memory")

__device__ __forceinline__ void mma_bf16(float* d, const uint32_t* a,
                                         const uint32_t* b) {
    asm volatile(
        "mma.sync.aligned.m16n8k16.row.col.f32.bf16.bf16.f32 "
        "{%0,%1,%2,%3}, {%4,%5,%6,%7}, {%8,%9}, {%0,%1,%2,%3};"
        : "+f"(d[0]), "+f"(d[1]), "+f"(d[2]), "+f"(d[3])
        : "r"(a[0]), "r"(a[1]), "r"(a[2]), "r"(a[3]), "r"(b[0]), "r"(b[1]));
}

__device__ __forceinline__ void split_pack(float x, float y, uint32_t& hi,
                                           uint32_t& lo) {
    __nv_bfloat16 hx = __float2bfloat16(x), hy = __float2bfloat16(y);
    __nv_bfloat162 h2(hx, hy);
    hi = *(uint32_t*)&h2;
    __nv_bfloat162 l2(__float2bfloat16(x - __bfloat162float(hx)),
                      __float2bfloat16(y - __bfloat162float(hy)));
    lo = *(uint32_t*)&l2;
}

__device__ __forceinline__ void split_store2(__nv_bfloat16* hi,
                                             __nv_bfloat16* lo, size_t idx,
                                             float x, float y) {
    uint32_t h, l;
    split_pack(x, y, h, l);
    *(uint32_t*)(hi + idx) = h;
    *(uint32_t*)(lo + idx) = l;
}

// ---------------- RoPE table ------------------------------------------------
__global__ void rope_init_kernel() {
    int idx = blockIdx.x * blockDim.x + threadIdx.x;
    if (idx >= SEQ * (HD / 2)) return;
    int pos = idx / (HD / 2);
    int i = idx % (HD / 2);
    double invd = pow(10000.0, -(double)(2 * i) / (double)HD);
    float inv = (float)invd;
    float ang = (float)pos * inv;
    g_cos[idx] = (float)cos((double)ang);
    g_sin[idx] = (float)sin((double)ang);
}

// ---------------- fp32 -> split bf16 conversion -----------------------------
__device__ __forceinline__ void split_store4(__nv_bfloat162* hi,
                                             __nv_bfloat162* lo, int i,
                                             float4 v) {
    __nv_bfloat16 h0 = __float2bfloat16(v.x);
    __nv_bfloat16 h1 = __float2bfloat16(v.y);
    __nv_bfloat16 h2 = __float2bfloat16(v.z);
    __nv_bfloat16 h3 = __float2bfloat16(v.w);
    hi[i * 2 + 0] = __nv_bfloat162(h0, h1);
    hi[i * 2 + 1] = __nv_bfloat162(h2, h3);
    lo[i * 2 + 0] = __nv_bfloat162(__float2bfloat16(v.x - __bfloat162float(h0)),
                                   __float2bfloat16(v.y - __bfloat162float(h1)));
    lo[i * 2 + 1] = __nv_bfloat162(__float2bfloat16(v.z - __bfloat162float(h2)),
                                   __float2bfloat16(v.w - __bfloat162float(h3)));
}

__global__ void convert_x_kernel(const float4* __restrict__ src) {
    int i = blockIdx.x * blockDim.x + threadIdx.x;
    if (i >= MROWS * E_DIM / 4) return;
    split_store4((__nv_bfloat162*)g_x_hi, (__nv_bfloat162*)g_x_lo, i, src[i]);
}

__global__ void convert_w_kernel(const float4* __restrict__ w0,
                                 const float4* __restrict__ w1,
                                 const float4* __restrict__ w2,
                                 const float4* __restrict__ w3) {
    int i = blockIdx.x * blockDim.x + threadIdx.x;
    if (i >= E_DIM * E_DIM / 4) return;
    int z = blockIdx.y;
    const float4* src = (z == 0) ? w0 : (z == 1) ? w1 : (z == 2) ? w2 : w3;
    split_store4((__nv_bfloat162*)(g_w_hi + (size_t)z * E_DIM * E_DIM),
                 (__nv_bfloat162*)(g_w_lo + (size_t)z * E_DIM * E_DIM), i, src[i]);
}

// ---------------- HMMA GEMM with cp.async 4-stage pipeline ------------------
#define GBM 128
#define GBN 128
#define GBK 16
#define NCHUNK (E_DIM / GBK) /* 128 */
#define BSTR 48
#define TILE_BYTES (128 * BSTR)      /* 6144 */
#define STAGE_BYTES (4 * TILE_BYTES) /* 24576 */
#define NSTAGE 4
#define GEMM_SMEM (NSTAGE * STAGE_BYTES) /* 98304 */

// mode: 0=Q (rope+scale), 1=K (rope), 2=V, 3=fp32 out
__device__ __forceinline__ void gemm_mma_body(
    const __nv_bfloat16* __restrict__ Ahi, const __nv_bfloat16* __restrict__ Alo,
    const __nv_bfloat16* __restrict__ Bhi, const __nv_bfloat16* __restrict__ Blo,
    float* __restrict__ Cout, int mode) {
    extern __shared__ char smem[];
    uint32_t sbase = smem_u32(smem);
    int tid = threadIdx.x;
    int wid = tid >> 5;
    int lane = tid & 31;
    int m0 = blockIdx.y * GBM;
    int n0 = blockIdx.x * GBN;
    int warp_m = (wid & 3) * 32;
    int warp_n = (wid >> 2) * 64;

    int gidx = lane >> 2;
    int ctg2 = (lane & 3) * 2;

    // per-thread staging coordinates
    int row = tid >> 1;
    int ce = (tid & 1) * 8;
    uint32_t soff = (uint32_t)(row * BSTR + (tid & 1) * 16);
    const __nv_bfloat16* pa_hi = Ahi + (size_t)(m0 + row) * E_DIM + ce;
    const __nv_bfloat16* pa_lo = Alo + (size_t)(m0 + row) * E_DIM + ce;
    const __nv_bfloat16* pb_hi = Bhi + (size_t)(n0 + row) * E_DIM + ce;
    const __nv_bfloat16* pb_lo = Blo + (size_t)(n0 + row) * E_DIM + ce;

    float acc[2][8][4];
#pragma unroll
    for (int mi = 0; mi < 2; mi++)
#pragma unroll
        for (int nj = 0; nj < 8; nj++)
#pragma unroll
            for (int q = 0; q < 4; q++) acc[mi][nj][q] = 0.f;

    // prologue: stages 0..2
#pragma unroll
    for (int s = 0; s < NSTAGE - 1; s++) {
        uint32_t st = sbase + s * STAGE_BYTES + soff;
        int k0 = s * GBK;
        cp_async16(st + 0 * TILE_BYTES, pa_hi + k0);
        cp_async16(st + 1 * TILE_BYTES, pa_lo + k0);
        cp_async16(st + 2 * TILE_BYTES, pb_hi + k0);
        cp_async16(st + 3 * TILE_BYTES, pb_lo + k0);
        CP_COMMIT();
    }

    for (int c = 0; c < NCHUNK; c++) {
        CP_WAIT2();
        __syncthreads();

        const char* st = smem + (c & (NSTAGE - 1)) * STAGE_BYTES;
        const char* sa_hi = st;
        const char* sa_lo = st + TILE_BYTES;
        const char* sb_hi = st + 2 * TILE_BYTES;
        const char* sb_lo = st + 3 * TILE_BYTES;

        uint32_t ahi[2][4], alo[2][4];
#pragma unroll
        for (int mi = 0; mi < 2; mi++) {
            int r0 = (warp_m + mi * 16 + gidx) * BSTR;
            int klo = ctg2 * 2;
            int khi = (ctg2 + 8) * 2;
            ahi[mi][0] = *(const uint32_t*)(sa_hi + r0 + klo);
            ahi[mi][1] = *(const uint32_t*)(sa_hi + r0 + 8 * BSTR + klo);
            ahi[mi][2] = *(const uint32_t*)(sa_hi + r0 + khi);
            ahi[mi][3] = *(const uint32_t*)(sa_hi + r0 + 8 * BSTR + khi);
            alo[mi][0] = *(const uint32_t*)(sa_lo + r0 + klo);
            alo[mi][1] = *(const uint32_t*)(sa_lo + r0 + 8 * BSTR + klo);
            alo[mi][2] = *(const uint32_t*)(sa_lo + r0 + khi);
            alo[mi][3] = *(const uint32_t*)(sa_lo + r0 + 8 * BSTR + khi);
        }
#pragma unroll
        for (int nj = 0; nj < 8; nj++) {
            int rb = (warp_n + nj * 8 + gidx) * BSTR;
            uint32_t bhi[2], blo[2];
            bhi[0] = *(const uint32_t*)(sb_hi + rb + ctg2 * 2);
            bhi[1] = *(const uint32_t*)(sb_hi + rb + (ctg2 + 8) * 2);
            blo[0] = *(const uint32_t*)(sb_lo + rb + ctg2 * 2);
            blo[1] = *(const uint32_t*)(sb_lo + rb + (ctg2 + 8) * 2);
#pragma unroll
            for (int mi = 0; mi < 2; mi++) {
                mma_bf16(acc[mi][nj], ahi[mi], bhi);
                mma_bf16(acc[mi][nj], ahi[mi], blo);
                mma_bf16(acc[mi][nj], alo[mi], bhi);
            }
        }

        // issue stage c+3 (empty commit near the tail keeps group count exact)
        if (c + NSTAGE - 1 < NCHUNK) {
            uint32_t sw = sbase + ((c + NSTAGE - 1) & (NSTAGE - 1)) * STAGE_BYTES + soff;
            int k0 = (c + NSTAGE - 1) * GBK;
            cp_async16(sw + 0 * TILE_BYTES, pa_hi + k0);
            cp_async16(sw + 1 * TILE_BYTES, pa_lo + k0);
            cp_async16(sw + 2 * TILE_BYTES, pb_hi + k0);
            cp_async16(sw + 3 * TILE_BYTES, pb_lo + k0);
        }
        CP_COMMIT();
    }

    int tig = lane & 3;
    __nv_bfloat16* dhi = (mode == 0) ? g_qhi : (mode == 1) ? g_khi : g_vhi;
    __nv_bfloat16* dlo = (mode == 0) ? g_qlo : (mode == 1) ? g_klo : g_vlo;
    const float qsc = (mode == 0) ? 0.08838834764831845f : 1.0f;

#pragma unroll
    for (int mi = 0; mi < 2; mi++) {
#pragma unroll
        for (int nj = 0; nj < 8; nj++) {
            int m = m0 + warp_m + mi * 16 + gidx;
            int n = n0 + warp_n + nj * 8 + tig * 2;
            float v0 = acc[mi][nj][0], v1 = acc[mi][nj][1];
            float v2 = acc[mi][nj][2], v3 = acc[mi][nj][3];
            if (mode <= 1) {
                int pi = (n & (HD - 1)) >> 1;
                int p0 = m & (SEQ - 1);
                int p8 = p0 + 8;
                float c0 = g_cos[p0 * (HD / 2) + pi], s0 = g_sin[p0 * (HD / 2) + pi];
                float c8 = g_cos[p8 * (HD / 2) + pi], s8 = g_sin[p8 * (HD / 2) + pi];
                float t0 = v0 * c0 - v1 * s0, t1 = v0 * s0 + v1 * c0;
                float t2 = v2 * c8 - v3 * s8, t3 = v2 * s8 + v3 * c8;
                v0 = t0 * qsc; v1 = t1 * qsc; v2 = t2 * qsc; v3 = t3 * qsc;
            }
            if (mode == 3) {
                *(float2*)&Cout[(size_t)m * E_DIM + n] = make_float2(v0, v1);
                *(float2*)&Cout[(size_t)(m + 8) * E_DIM + n] = make_float2(v2, v3);
            } else {
                int b = m >> 11, s = m & 2047, h = n >> 7, d = n & 127;
                size_t base0 = ((size_t)(b * NHEAD + h) * SEQ + s) * HD + d;
                size_t base1 = base0 + 8 * HD;
                split_store2(dhi, dlo, base0, v0, v1);
                split_store2(dhi, dlo, base1, v2, v3);
            }
        }
    }
}

__global__ __launch_bounds__(256, 2) void gemm_qkv_tc(void) {
    int z = blockIdx.z;
    const __nv_bfloat16* bh = g_w_hi + (size_t)z * E_DIM * E_DIM;
    const __nv_bfloat16* bl = g_w_lo + (size_t)z * E_DIM * E_DIM;
    gemm_mma_body(g_x_hi, g_x_lo, bh, bl, nullptr, z);
}

__global__ __launch_bounds__(256, 2) void gemm_out_tc(float* __restrict__ out) {
    const __nv_bfloat16* bh = g_w_hi + (size_t)3 * E_DIM * E_DIM;
    const __nv_bfloat16* bl = g_w_lo + (size_t)3 * E_DIM * E_DIM;
    gemm_mma_body(g_attn_hi, g_attn_lo, bh, bl, out, 3);
}

// ---------------- V transpose: [bh][s][d] -> [bh][d][s] ---------------------
__global__ void transpose_v_kernel() {
    __shared__ __nv_bfloat16 t[32][33];
    int bh = blockIdx.z >> 1;
    const __nv_bfloat16* src = (blockIdx.z & 1) ? g_vlo : g_vhi;
    __nv_bfloat16* dst = (blockIdx.z & 1) ? g_vtlo : g_vthi;
    int tx = threadIdx.x, ty = threadIdx.y;
    int s0 = blockIdx.x * 32, d0 = blockIdx.y * 32;
#pragma unroll
    for (int i = 0; i < 32; i += 8)
        t[ty + i][tx] = src[((size_t)bh * SEQ + s0 + ty + i) * HD + d0 + tx];
    __syncthreads();
#pragma unroll
    for (int i = 0; i < 32; i += 8)
        dst[((size_t)bh * HD + d0 + ty + i) * SEQ + s0 + tx] = t[tx][ty + i];
}

// ---------------- Tensor-core flash attention (causal) ----------------------
#define KSTR_B 272
#define VSTR_B 144
#define SM_KHI 0
#define SM_KLO (64 * KSTR_B)
#define SM_VHI (2 * 64 * KSTR_B)
#define SM_VLO (SM_VHI + 128 * VSTR_B)
#define FLASH_SMEM (SM_VLO + 128 * VSTR_B) /* 71680 */

__global__ __launch_bounds__(128) void flash_mma_kernel() {
    extern __shared__ char sm[];
    char* skhi = sm + SM_KHI;
    char* sklo = sm + SM_KLO;
    char* svhi = sm + SM_VHI;
    char* svlo = sm + SM_VLO;

    int tid = threadIdx.x;
    int wid = tid >> 5;
    int lane = tid & 31;
    int qt = (int)gridDim.x - 1 - (int)blockIdx.x;
    int bh = blockIdx.y;
    int g = lane >> 2;
    int c = lane & 3;
    int warp_m = wid * 16;

    uint32_t qh[8][4], ql[8][4];
    {
        const __nv_bfloat16* Qh = g_qhi + (size_t)bh * SEQ * HD + (size_t)qt * 64 * HD;
        const __nv_bfloat16* Ql = g_qlo + (size_t)bh * SEQ * HD + (size_t)qt * 64 * HD;
        int r0 = (warp_m + g) * HD, r1 = (warp_m + g + 8) * HD;
#pragma unroll
        for (int kc = 0; kc < 8; kc++) {
            int c0 = kc * 16 + c * 2, c1 = c0 + 8;
            qh[kc][0] = *(const uint32_t*)(Qh + r0 + c0);
            qh[kc][1] = *(const uint32_t*)(Qh + r1 + c0);
            qh[kc][2] = *(const uint32_t*)(Qh + r0 + c1);
            qh[kc][3] = *(const uint32_t*)(Qh + r1 + c1);
            ql[kc][0] = *(const uint32_t*)(Ql + r0 + c0);
            ql[kc][1] = *(const uint32_t*)(Ql + r1 + c0);
            ql[kc][2] = *(const uint32_t*)(Ql + r0 + c1);
            ql[kc][3] = *(const uint32_t*)(Ql + r1 + c1);
        }
    }

    float o[16][4];
#pragma unroll
    for (int t = 0; t < 16; t++)
#pragma unroll
        for (int q = 0; q < 4; q++) o[t][q] = 0.f;
    float m0 = -1e30f, m1 = -1e30f, l0 = 0.f, l1 = 0.f;

    const __nv_bfloat16* Kh = g_khi + (size_t)bh * SEQ * HD;
    const __nv_bfloat16* Kl = g_klo + (size_t)bh * SEQ * HD;
    const __nv_bfloat16* Vh = g_vthi + (size_t)bh * HD * SEQ;
    const __nv_bfloat16* Vl = g_vtlo + (size_t)bh * HD * SEQ;

    for (int kt = 0; kt <= qt; kt++) {
        __syncthreads();
        {
            const uint4* srch = (const uint4*)(Kh + (size_t)kt * 64 * HD);
            const uint4* srcl = (const uint4*)(Kl + (size_t)kt * 64 * HD);
#pragma unroll
            for (int i = 0; i < 8; i++) {
                int idx = tid + i * 128;
                int row = idx >> 4, cc = idx & 15;
                *(uint4*)(skhi + row * KSTR_B + cc * 16) = srch[idx];
                *(uint4*)(sklo + row * KSTR_B + cc * 16) = srcl[idx];
            }
#pragma unroll
            for (int i = 0; i < 8; i++) {
                int idx = tid + i * 128;
                int row = idx >> 3, cc = idx & 7;
                const uint4* vrh = (const uint4*)(Vh + (size_t)row * SEQ + kt * 64);
                const uint4* vrl = (const uint4*)(Vl + (size_t)row * SEQ + kt * 64);
                *(uint4*)(svhi + row * VSTR_B + cc * 16) = vrh[cc];
                *(uint4*)(svlo + row * VSTR_B + cc * 16) = vrl[cc];
            }
        }
        __syncthreads();

        float s_acc[8][4];
#pragma unroll
        for (int nj = 0; nj < 8; nj++)
#pragma unroll
            for (int q = 0; q < 4; q++) s_acc[nj][q] = 0.f;

#pragma unroll
        for (int kc = 0; kc < 8; kc++) {
#pragma unroll
            for (int nj = 0; nj < 8; nj++) {
                int off = (nj * 8 + g) * KSTR_B + kc * 32 + c * 4;
                uint32_t bh2[2], bl2[2];
                bh2[0] = *(const uint32_t*)(skhi + off);
                bh2[1] = *(const uint32_t*)(skhi + off + 16);
                bl2[0] = *(const uint32_t*)(sklo + off);
                bl2[1] = *(const uint32_t*)(sklo + off + 16);
                mma_bf16(s_acc[nj], qh[kc], bh2);
                mma_bf16(s_acc[nj], qh[kc], bl2);
                mma_bf16(s_acc[nj], ql[kc], bh2);
            }
        }

        if (kt == qt) {
            int row0 = warp_m + g, row1 = row0 + 8;
#pragma unroll
            for (int nj = 0; nj < 8; nj++) {
                int col = nj * 8 + c * 2;
                if (col > row0) s_acc[nj][0] = -1e30f;
                if (col + 1 > row0) s_acc[nj][1] = -1e30f;
                if (col > row1) s_acc[nj][2] = -1e30f;
                if (col + 1 > row1) s_acc[nj][3] = -1e30f;
            }
        }

        float mt0 = -1e30f, mt1 = -1e30f;
#pragma unroll
        for (int nj = 0; nj < 8; nj++) {
            mt0 = fmaxf(mt0, fmaxf(s_acc[nj][0], s_acc[nj][1]));
            mt1 = fmaxf(mt1, fmaxf(s_acc[nj][2], s_acc[nj][3]));
        }
        mt0 = fmaxf(mt0, __shfl_xor_sync(0xffffffffu, mt0, 1));
        mt0 = fmaxf(mt0, __shfl_xor_sync(0xffffffffu, mt0, 2));
        mt1 = fmaxf(mt1, __shfl_xor_sync(0xffffffffu, mt1, 1));
        mt1 = fmaxf(mt1, __shfl_xor_sync(0xffffffffu, mt1, 2));
        float mn0 = fmaxf(m0, mt0), mn1 = fmaxf(m1, mt1);
        float a0 = __expf(m0 - mn0), a1 = __expf(m1 - mn1);
        m0 = mn0; m1 = mn1;
#pragma unroll
        for (int t = 0; t < 16; t++) {
            o[t][0] *= a0; o[t][1] *= a0;
            o[t][2] *= a1; o[t][3] *= a1;
        }
        float rs0 = 0.f, rs1 = 0.f;
#pragma unroll
        for (int nj = 0; nj < 8; nj++) {
            float p0 = __expf(s_acc[nj][0] - mn0);
            float p1 = __expf(s_acc[nj][1] - mn0);
            float p2 = __expf(s_acc[nj][2] - mn1);
            float p3 = __expf(s_acc[nj][3] - mn1);
            s_acc[nj][0] = p0; s_acc[nj][1] = p1;
            s_acc[nj][2] = p2; s_acc[nj][3] = p3;
            rs0 += p0 + p1; rs1 += p2 + p3;
        }
        l0 = l0 * a0 + rs0;
        l1 = l1 * a1 + rs1;

        uint32_t ph[4][4], pl[4][4];
#pragma unroll
        for (int kc = 0; kc < 4; kc++) {
            split_pack(s_acc[2 * kc][0], s_acc[2 * kc][1], ph[kc][0], pl[kc][0]);
            split_pack(s_acc[2 * kc][2], s_acc[2 * kc][3], ph[kc][1], pl[kc][1]);
            split_pack(s_acc[2 * kc + 1][0], s_acc[2 * kc + 1][1], ph[kc][2], pl[kc][2]);
            split_pack(s_acc[2 * kc + 1][2], s_acc[2 * kc + 1][3], ph[kc][3], pl[kc][3]);
        }

#pragma unroll
        for (int nj = 0; nj < 16; nj++) {
#pragma unroll
            for (int kc = 0; kc < 4; kc++) {
                int off = (nj * 8 + g) * VSTR_B + kc * 32 + c * 4;
                uint32_t vh2[2], vl2[2];
                vh2[0] = *(const uint32_t*)(svhi + off);
                vh2[1] = *(const uint32_t*)(svhi + off + 16);
                vl2[0] = *(const uint32_t*)(svlo + off);
                vl2[1] = *(const uint32_t*)(svlo + off + 16);
                mma_bf16(o[nj], ph[kc], vh2);
                mma_bf16(o[nj], ph[kc], vl2);
                mma_bf16(o[nj], pl[kc], vh2);
            }
        }
    }

    l0 += __shfl_xor_sync(0xffffffffu, l0, 1);
    l0 += __shfl_xor_sync(0xffffffffu, l0, 2);
    l1 += __shfl_xor_sync(0xffffffffu, l1, 1);
    l1 += __shfl_xor_sync(0xffffffffu, l1, 2);
    float i0 = 1.0f / l0, i1 = 1.0f / l1;
    int b = bh >> 4, h = bh & 15;
    int s0 = qt * 64 + warp_m + g;
    size_t r0 = ((size_t)b * SEQ + s0) * E_DIM + h * HD;
    size_t r1 = ((size_t)b * SEQ + s0 + 8) * E_DIM + h * HD;
#pragma unroll
    for (int nj = 0; nj < 16; nj++) {
        int d = nj * 8 + c * 2;
        split_store2(g_attn_hi, g_attn_lo, r0 + d, o[nj][0] * i0, o[nj][1] * i0);
        split_store2(g_attn_hi, g_attn_lo, r1 + d, o[nj][2] * i1, o[nj][3] * i1);
    }
}

// ---------------- launcher ---------------------------------------------------
extern "C" void kernel_launch(void* const* d_in, const int* in_sizes, int n_in,
                              void* d_out, int out_size) {
    const float* x = (const float*)d_in[0];
    const float* Wq = (const float*)d_in[1];
    const float* Wk = (const float*)d_in[2];
    const float* Wv = (const float*)d_in[3];
    const float* Wo = (const float*)d_in[4];
    float* out = (float*)d_out;

    cudaFuncSetAttribute(gemm_qkv_tc, cudaFuncAttributeMaxDynamicSharedMemorySize,
                         GEMM_SMEM);
    cudaFuncSetAttribute(gemm_out_tc, cudaFuncAttributeMaxDynamicSharedMemorySize,
                         GEMM_SMEM);
    cudaFuncSetAttribute(flash_mma_kernel,
                         cudaFuncAttributeMaxDynamicSharedMemorySize, FLASH_SMEM);

    rope_init_kernel<<<(SEQ * (HD / 2) + 255) / 256, 256>>>();

    {
        int n4 = MROWS * E_DIM / 4;
        convert_x_kernel<<<(n4 + 255) / 256, 256>>>((const float4*)x);
        int w4 = E_DIM * E_DIM / 4;
        dim3 gw((w4 + 255) / 256, 4);
        convert_w_kernel<<<gw, 256>>>((const float4*)Wq, (const float4*)Wk,
                                      (const float4*)Wv, (const float4*)Wo);
    }

    dim3 gqkv(E_DIM / GBN, MROWS / GBM, 3);
    gemm_qkv_tc<<<gqkv, 256, GEMM_SMEM>>>();

    dim3 gtr(SEQ / 32, HD / 32, NBATCH * NHEAD * 2);
    transpose_v_kernel<<<gtr, dim3(32, 8)>>>();

    dim3 gfa(SEQ / 64, NBATCH * NHEAD);
    flash_mma_kernel<<<gfa, 128, FLASH_SMEM>>>();

    dim3 gout(E_DIM / GBN, MROWS / GBM);
    gemm_out_tc<<<gout, 256, GEMM_SMEM>>>(out);
}

// round 8
// speedup vs baseline: 5.1107x; 1.0956x over previous
#include <cuda_runtime.h>
#include <cuda_bf16.h>
#include <math.h>
#include <stdint.h>

#define E_DIM 2048
#define SEQ 2048
#define NBATCH 2
#define NHEAD 16
#define HD 128
#define MROWS (NBATCH * SEQ) /* 4096 */

// ---------------- scratch (device globals; no allocation allowed) ----------
__device__ __nv_bfloat16 g_x_hi[MROWS * E_DIM];
__device__ __nv_bfloat16 g_x_lo[MROWS * E_DIM];
__device__ __nv_bfloat16 g_w_hi[4 * E_DIM * E_DIM];
__device__ __nv_bfloat16 g_w_lo[4 * E_DIM * E_DIM];
__device__ __nv_bfloat16 g_qhi[MROWS * E_DIM];
__device__ __nv_bfloat16 g_qlo[MROWS * E_DIM];
__device__ __nv_bfloat16 g_khi[MROWS * E_DIM];
__device__ __nv_bfloat16 g_klo[MROWS * E_DIM];
__device__ __nv_bfloat16 g_vhi[MROWS * E_DIM];
__device__ __nv_bfloat16 g_vlo[MROWS * E_DIM];
__device__ __nv_bfloat16 g_vthi[MROWS * E_DIM];
__device__ __nv_bfloat16 g_vtlo[MROWS * E_DIM];
__device__ __nv_bfloat16 g_attn_hi[MROWS * E_DIM];
__device__ __nv_bfloat16 g_attn_lo[MROWS * E_DIM];
__device__ float g_cos[SEQ * (HD / 2)];
__device__ float g_sin[SEQ * (HD / 2)];

// ---------------- helpers ----------------------------------------------------
__device__ __forceinline__ uint32_t smem_u32(const void* p) {
    uint32_t a;
    asm("{ .reg .u64 t; cvta.to.shared.u64 t, %1; cvt.u32.u64 %0, t; }"
        : "=r"(a) : "l"(p));
    return a;
}
__device__ __forceinline__ void cp_async16(uint32_t dst, const void* src) {
    asm volatile("cp.async.cg.shared.global [%0], [%1], 16;"
                 :: "r"(dst), "l"(src));
}
#define CP_COMMIT() asm volatile("cp.async.commit_group;" ::: "memory")
#define CP_WAIT2() asm volatile("cp.async.wait_group 2;" ::: "memory")

__device__ __forceinline__ void ldsm_x4(uint32_t addr, uint32_t* r) {
    asm volatile("ldmatrix.sync.aligned.m8n8.x4.shared.b16 {%0,%1,%2,%3}, [%4];"
                 : "=r"(r[0]), "=r"(r[1]), "=r"(r[2]), "=r"(r[3]) : "r"(addr));
}

__device__ __forceinline__ void mma_bf16(float* d, const uint32_t* a,
                                         const uint32_t* b) {
    asm volatile(
        "mma.sync.aligned.m16n8k16.row.col.f32.bf16.bf16.f32 "
        "{%0,%1,%2,%3}, {%4,%5,%6,%7}, {%8,%9}, {%0,%1,%2,%3};"
        : "+f"(d[0]), "+f"(d[1]), "+f"(d[2]), "+f"(d[3])
        : "r"(a[0]), "r"(a[1]), "r"(a[2]), "r"(a[3]), "r"(b[0]), "r"(b[1]));
}

__device__ __forceinline__ void split_pack(float x, float y, uint32_t& hi,
                                           uint32_t& lo) {
    __nv_bfloat16 hx = __float2bfloat16(x), hy = __float2bfloat16(y);
    __nv_bfloat162 h2(hx, hy);
    hi = *(uint32_t*)&h2;
    __nv_bfloat162 l2(__float2bfloat16(x - __bfloat162float(hx)),
                      __float2bfloat16(y - __bfloat162float(hy)));
    lo = *(uint32_t*)&l2;
}

__device__ __forceinline__ void split_store2(__nv_bfloat16* hi,
                                             __nv_bfloat16* lo, size_t idx,
                                             float x, float y) {
    uint32_t h, l;
    split_pack(x, y, h, l);
    *(uint32_t*)(hi + idx) = h;
    *(uint32_t*)(lo + idx) = l;
}

// ---------------- RoPE table ------------------------------------------------
__global__ void rope_init_kernel() {
    int idx = blockIdx.x * blockDim.x + threadIdx.x;
    if (idx >= SEQ * (HD / 2)) return;
    int pos = idx / (HD / 2);
    int i = idx % (HD / 2);
    double invd = pow(10000.0, -(double)(2 * i) / (double)HD);
    float inv = (float)invd;
    float ang = (float)pos * inv;
    g_cos[idx] = (float)cos((double)ang);
    g_sin[idx] = (float)sin((double)ang);
}

// ---------------- fp32 -> split bf16 conversion -----------------------------
__device__ __forceinline__ void split_store4(__nv_bfloat162* hi,
                                             __nv_bfloat162* lo, int i,
                                             float4 v) {
    __nv_bfloat16 h0 = __float2bfloat16(v.x);
    __nv_bfloat16 h1 = __float2bfloat16(v.y);
    __nv_bfloat16 h2 = __float2bfloat16(v.z);
    __nv_bfloat16 h3 = __float2bfloat16(v.w);
    hi[i * 2 + 0] = __nv_bfloat162(h0, h1);
    hi[i * 2 + 1] = __nv_bfloat162(h2, h3);
    lo[i * 2 + 0] = __nv_bfloat162(__float2bfloat16(v.x - __bfloat162float(h0)),
                                   __float2bfloat16(v.y - __bfloat162float(h1)));
    lo[i * 2 + 1] = __nv_bfloat162(__float2bfloat16(v.z - __bfloat162float(h2)),
                                   __float2bfloat16(v.w - __bfloat162float(h3)));
}

__global__ void convert_x_kernel(const float4* __restrict__ src) {
    int i = blockIdx.x * blockDim.x + threadIdx.x;
    if (i >= MROWS * E_DIM / 4) return;
    split_store4((__nv_bfloat162*)g_x_hi, (__nv_bfloat162*)g_x_lo, i, src[i]);
}

__global__ void convert_w_kernel(const float4* __restrict__ w0,
                                 const float4* __restrict__ w1,
                                 const float4* __restrict__ w2,
                                 const float4* __restrict__ w3) {
    int i = blockIdx.x * blockDim.x + threadIdx.x;
    if (i >= E_DIM * E_DIM / 4) return;
    int z = blockIdx.y;
    const float4* src = (z == 0) ? w0 : (z == 1) ? w1 : (z == 2) ? w2 : w3;
    split_store4((__nv_bfloat162*)(g_w_hi + (size_t)z * E_DIM * E_DIM),
                 (__nv_bfloat162*)(g_w_lo + (size_t)z * E_DIM * E_DIM), i, src[i]);
}

// ---------------- HMMA GEMM: cp.async 4-stage + ldmatrix --------------------
#define GBM 128
#define GBN 128
#define GBK 16
#define NCHUNK (E_DIM / GBK) /* 128 */
#define BSTR 48
#define TILE_BYTES (128 * BSTR)      /* 6144 */
#define STAGE_BYTES (4 * TILE_BYTES) /* 24576 */
#define NSTAGE 4
#define GEMM_SMEM (NSTAGE * STAGE_BYTES) /* 98304 */

// mode: 0=Q (rope+scale), 1=K (rope), 2=V, 3=fp32 out
__device__ __forceinline__ void gemm_mma_body(
    const __nv_bfloat16* __restrict__ Ahi, const __nv_bfloat16* __restrict__ Alo,
    const __nv_bfloat16* __restrict__ Bhi, const __nv_bfloat16* __restrict__ Blo,
    float* __restrict__ Cout, int mode) {
    extern __shared__ char smem[];
    uint32_t sbase = smem_u32(smem);
    int tid = threadIdx.x;
    int wid = tid >> 5;
    int lane = tid & 31;
    int m0 = blockIdx.y * GBM;
    int n0 = blockIdx.x * GBN;
    int warp_m = (wid & 3) * 32;
    int warp_n = (wid >> 2) * 64;

    int gidx = lane >> 2;

    // ldmatrix lane address offsets
    int a_row = (lane & 7) + ((lane >> 3) & 1) * 8;
    int a_col = (lane >> 4) * 16;  // bytes
    uint32_t a_off[2];
#pragma unroll
    for (int mi = 0; mi < 2; mi++)
        a_off[mi] = (uint32_t)((warp_m + mi * 16 + a_row) * BSTR + a_col);
    int b_row = (lane & 7) + ((lane >> 4) & 1) * 8;
    int b_col = ((lane >> 3) & 1) * 16;
    uint32_t b_off[4];
#pragma unroll
    for (int njp = 0; njp < 4; njp++)
        b_off[njp] = (uint32_t)((warp_n + njp * 16 + b_row) * BSTR + b_col);

    // staging coordinates
    int row = tid >> 1;
    int ce = (tid & 1) * 8;
    uint32_t soff = (uint32_t)(row * BSTR + (tid & 1) * 16);
    const __nv_bfloat16* pa_hi = Ahi + (size_t)(m0 + row) * E_DIM + ce;
    const __nv_bfloat16* pa_lo = Alo + (size_t)(m0 + row) * E_DIM + ce;
    const __nv_bfloat16* pb_hi = Bhi + (size_t)(n0 + row) * E_DIM + ce;
    const __nv_bfloat16* pb_lo = Blo + (size_t)(n0 + row) * E_DIM + ce;

    float acc[2][8][4];
#pragma unroll
    for (int mi = 0; mi < 2; mi++)
#pragma unroll
        for (int nj = 0; nj < 8; nj++)
#pragma unroll
            for (int q = 0; q < 4; q++) acc[mi][nj][q] = 0.f;

#pragma unroll
    for (int s = 0; s < NSTAGE - 1; s++) {
        uint32_t st = sbase + s * STAGE_BYTES + soff;
        int k0 = s * GBK;
        cp_async16(st + 0 * TILE_BYTES, pa_hi + k0);
        cp_async16(st + 1 * TILE_BYTES, pa_lo + k0);
        cp_async16(st + 2 * TILE_BYTES, pb_hi + k0);
        cp_async16(st + 3 * TILE_BYTES, pb_lo + k0);
        CP_COMMIT();
    }

    for (int c = 0; c < NCHUNK; c++) {
        CP_WAIT2();
        __syncthreads();

        uint32_t st = sbase + (uint32_t)(c & (NSTAGE - 1)) * STAGE_BYTES;

        uint32_t ahi[2][4], alo[2][4];
#pragma unroll
        for (int mi = 0; mi < 2; mi++) {
            ldsm_x4(st + a_off[mi], ahi[mi]);
            ldsm_x4(st + TILE_BYTES + a_off[mi], alo[mi]);
        }
#pragma unroll
        for (int njp = 0; njp < 4; njp++) {
            uint32_t bh4[4], bl4[4];
            ldsm_x4(st + 2 * TILE_BYTES + b_off[njp], bh4);
            ldsm_x4(st + 3 * TILE_BYTES + b_off[njp], bl4);
#pragma unroll
            for (int h = 0; h < 2; h++) {
                int nj = njp * 2 + h;
#pragma unroll
                for (int mi = 0; mi < 2; mi++) {
                    mma_bf16(acc[mi][nj], ahi[mi], bh4 + 2 * h);
                    mma_bf16(acc[mi][nj], ahi[mi], bl4 + 2 * h);
                    mma_bf16(acc[mi][nj], alo[mi], bh4 + 2 * h);
                }
            }
        }

        if (c + NSTAGE - 1 < NCHUNK) {
            uint32_t sw = sbase + ((c + NSTAGE - 1) & (NSTAGE - 1)) * STAGE_BYTES + soff;
            int k0 = (c + NSTAGE - 1) * GBK;
            cp_async16(sw + 0 * TILE_BYTES, pa_hi + k0);
            cp_async16(sw + 1 * TILE_BYTES, pa_lo + k0);
            cp_async16(sw + 2 * TILE_BYTES, pb_hi + k0);
            cp_async16(sw + 3 * TILE_BYTES, pb_lo + k0);
        }
        CP_COMMIT();
    }

    int tig = lane & 3;
    __nv_bfloat16* dhi = (mode == 0) ? g_qhi : (mode == 1) ? g_khi : g_vhi;
    __nv_bfloat16* dlo = (mode == 0) ? g_qlo : (mode == 1) ? g_klo : g_vlo;
    const float qsc = (mode == 0) ? 0.08838834764831845f : 1.0f;

#pragma unroll
    for (int mi = 0; mi < 2; mi++) {
#pragma unroll
        for (int nj = 0; nj < 8; nj++) {
            int m = m0 + warp_m + mi * 16 + gidx;
            int n = n0 + warp_n + nj * 8 + tig * 2;
            float v0 = acc[mi][nj][0], v1 = acc[mi][nj][1];
            float v2 = acc[mi][nj][2], v3 = acc[mi][nj][3];
            if (mode <= 1) {
                int pi = (n & (HD - 1)) >> 1;
                int p0 = m & (SEQ - 1);
                int p8 = p0 + 8;
                float c0 = g_cos[p0 * (HD / 2) + pi], s0 = g_sin[p0 * (HD / 2) + pi];
                float c8 = g_cos[p8 * (HD / 2) + pi], s8 = g_sin[p8 * (HD / 2) + pi];
                float t0 = v0 * c0 - v1 * s0, t1 = v0 * s0 + v1 * c0;
                float t2 = v2 * c8 - v3 * s8, t3 = v2 * s8 + v3 * c8;
                v0 = t0 * qsc; v1 = t1 * qsc; v2 = t2 * qsc; v3 = t3 * qsc;
            }
            if (mode == 3) {
                *(float2*)&Cout[(size_t)m * E_DIM + n] = make_float2(v0, v1);
                *(float2*)&Cout[(size_t)(m + 8) * E_DIM + n] = make_float2(v2, v3);
            } else {
                int b = m >> 11, s = m & 2047, h = n >> 7, d = n & 127;
                size_t base0 = ((size_t)(b * NHEAD + h) * SEQ + s) * HD + d;
                size_t base1 = base0 + 8 * HD;
                split_store2(dhi, dlo, base0, v0, v1);
                split_store2(dhi, dlo, base1, v2, v3);
            }
        }
    }
}

__global__ __launch_bounds__(256, 2) void gemm_qkv_tc(void) {
    int z = blockIdx.z;
    const __nv_bfloat16* bh = g_w_hi + (size_t)z * E_DIM * E_DIM;
    const __nv_bfloat16* bl = g_w_lo + (size_t)z * E_DIM * E_DIM;
    gemm_mma_body(g_x_hi, g_x_lo, bh, bl, nullptr, z);
}

__global__ __launch_bounds__(256, 2) void gemm_out_tc(float* __restrict__ out) {
    const __nv_bfloat16* bh = g_w_hi + (size_t)3 * E_DIM * E_DIM;
    const __nv_bfloat16* bl = g_w_lo + (size_t)3 * E_DIM * E_DIM;
    gemm_mma_body(g_attn_hi, g_attn_lo, bh, bl, out, 3);
}

// ---------------- V transpose: [bh][s][d] -> [bh][d][s] ---------------------
__global__ void transpose_v_kernel() {
    __shared__ __nv_bfloat16 t[32][33];
    int bh = blockIdx.z >> 1;
    const __nv_bfloat16* src = (blockIdx.z & 1) ? g_vlo : g_vhi;
    __nv_bfloat16* dst = (blockIdx.z & 1) ? g_vtlo : g_vthi;
    int tx = threadIdx.x, ty = threadIdx.y;
    int s0 = blockIdx.x * 32, d0 = blockIdx.y * 32;
#pragma unroll
    for (int i = 0; i < 32; i += 8)
        t[ty + i][tx] = src[((size_t)bh * SEQ + s0 + ty + i) * HD + d0 + tx];
    __syncthreads();
#pragma unroll
    for (int i = 0; i < 32; i += 8)
        dst[((size_t)bh * HD + d0 + ty + i) * SEQ + s0 + tx] = t[tx][ty + i];
}

// ---------------- Tensor-core flash attention (causal) ----------------------
#define KSTR_B 272
#define VSTR_B 144
#define SM_KHI 0
#define SM_KLO (64 * KSTR_B)
#define SM_VHI (2 * 64 * KSTR_B)
#define SM_VLO (SM_VHI + 128 * VSTR_B)
#define FLASH_SMEM (SM_VLO + 128 * VSTR_B) /* 71680 */

__global__ __launch_bounds__(128) void flash_mma_kernel() {
    extern __shared__ char sm[];
    uint32_t sm32 = smem_u32(sm);

    int tid = threadIdx.x;
    int wid = tid >> 5;
    int lane = tid & 31;
    int qt = (int)gridDim.x - 1 - (int)blockIdx.x;
    int bh = blockIdx.y;
    int g = lane >> 2;
    int c = lane & 3;
    int warp_m = wid * 16;

    // ldmatrix lane offsets (B-operand pattern: rows=n, m2/m3 = nj+1)
    int b_row = (lane & 7) + ((lane >> 4) & 1) * 8;
    int b_col = ((lane >> 3) & 1) * 16;
    uint32_t k_off[4], v_off[8];
#pragma unroll
    for (int njp = 0; njp < 4; njp++)
        k_off[njp] = (uint32_t)((njp * 16 + b_row) * KSTR_B + b_col);
#pragma unroll
    for (int njp = 0; njp < 8; njp++)
        v_off[njp] = (uint32_t)((njp * 16 + b_row) * VSTR_B + b_col);

    uint32_t qh[8][4], ql[8][4];
    {
        const __nv_bfloat16* Qh = g_qhi + (size_t)bh * SEQ * HD + (size_t)qt * 64 * HD;
        const __nv_bfloat16* Ql = g_qlo + (size_t)bh * SEQ * HD + (size_t)qt * 64 * HD;
        int r0 = (warp_m + g) * HD, r1 = (warp_m + g + 8) * HD;
#pragma unroll
        for (int kc = 0; kc < 8; kc++) {
            int c0 = kc * 16 + c * 2, c1 = c0 + 8;
            qh[kc][0] = *(const uint32_t*)(Qh + r0 + c0);
            qh[kc][1] = *(const uint32_t*)(Qh + r1 + c0);
            qh[kc][2] = *(const uint32_t*)(Qh + r0 + c1);
            qh[kc][3] = *(const uint32_t*)(Qh + r1 + c1);
            ql[kc][0] = *(const uint32_t*)(Ql + r0 + c0);
            ql[kc][1] = *(const uint32_t*)(Ql + r1 + c0);
            ql[kc][2] = *(const uint32_t*)(Ql + r0 + c1);
            ql[kc][3] = *(const uint32_t*)(Ql + r1 + c1);
        }
    }

    float o[16][4];
#pragma unroll
    for (int t = 0; t < 16; t++)
#pragma unroll
        for (int q = 0; q < 4; q++) o[t][q] = 0.f;
    float m0 = -1e30f, m1 = -1e30f, l0 = 0.f, l1 = 0.f;

    const __nv_bfloat16* Kh = g_khi + (size_t)bh * SEQ * HD;
    const __nv_bfloat16* Kl = g_klo + (size_t)bh * SEQ * HD;
    const __nv_bfloat16* Vh = g_vthi + (size_t)bh * HD * SEQ;
    const __nv_bfloat16* Vl = g_vtlo + (size_t)bh * HD * SEQ;

    for (int kt = 0; kt <= qt; kt++) {
        __syncthreads();
        {
            char* skhi = sm + SM_KHI;
            char* sklo = sm + SM_KLO;
            char* svhi = sm + SM_VHI;
            char* svlo = sm + SM_VLO;
            const uint4* srch = (const uint4*)(Kh + (size_t)kt * 64 * HD);
            const uint4* srcl = (const uint4*)(Kl + (size_t)kt * 64 * HD);
#pragma unroll
            for (int i = 0; i < 8; i++) {
                int idx = tid + i * 128;
                int row = idx >> 4, cc = idx & 15;
                *(uint4*)(skhi + row * KSTR_B + cc * 16) = srch[idx];
                *(uint4*)(sklo + row * KSTR_B + cc * 16) = srcl[idx];
            }
#pragma unroll
            for (int i = 0; i < 8; i++) {
                int idx = tid + i * 128;
                int row = idx >> 3, cc = idx & 7;
                const uint4* vrh = (const uint4*)(Vh + (size_t)row * SEQ + kt * 64);
                const uint4* vrl = (const uint4*)(Vl + (size_t)row * SEQ + kt * 64);
                *(uint4*)(svhi + row * VSTR_B + cc * 16) = vrh[cc];
                *(uint4*)(svlo + row * VSTR_B + cc * 16) = vrl[cc];
            }
        }
        __syncthreads();

        float s_acc[8][4];
#pragma unroll
        for (int nj = 0; nj < 8; nj++)
#pragma unroll
            for (int q = 0; q < 4; q++) s_acc[nj][q] = 0.f;

#pragma unroll
        for (int kc = 0; kc < 8; kc++) {
#pragma unroll
            for (int njp = 0; njp < 4; njp++) {
                uint32_t bh4[4], bl4[4];
                ldsm_x4(sm32 + SM_KHI + k_off[njp] + kc * 32, bh4);
                ldsm_x4(sm32 + SM_KLO + k_off[njp] + kc * 32, bl4);
#pragma unroll
                for (int h = 0; h < 2; h++) {
                    int nj = njp * 2 + h;
                    mma_bf16(s_acc[nj], qh[kc], bh4 + 2 * h);
                    mma_bf16(s_acc[nj], qh[kc], bl4 + 2 * h);
                    mma_bf16(s_acc[nj], ql[kc], bh4 + 2 * h);
                }
            }
        }

        if (kt == qt) {
            int row0 = warp_m + g, row1 = row0 + 8;
#pragma unroll
            for (int nj = 0; nj < 8; nj++) {
                int col = nj * 8 + c * 2;
                if (col > row0) s_acc[nj][0] = -1e30f;
                if (col + 1 > row0) s_acc[nj][1] = -1e30f;
                if (col > row1) s_acc[nj][2] = -1e30f;
                if (col + 1 > row1) s_acc[nj][3] = -1e30f;
            }
        }

        float mt0 = -1e30f, mt1 = -1e30f;
#pragma unroll
        for (int nj = 0; nj < 8; nj++) {
            mt0 = fmaxf(mt0, fmaxf(s_acc[nj][0], s_acc[nj][1]));
            mt1 = fmaxf(mt1, fmaxf(s_acc[nj][2], s_acc[nj][3]));
        }
        mt0 = fmaxf(mt0, __shfl_xor_sync(0xffffffffu, mt0, 1));
        mt0 = fmaxf(mt0, __shfl_xor_sync(0xffffffffu, mt0, 2));
        mt1 = fmaxf(mt1, __shfl_xor_sync(0xffffffffu, mt1, 1));
        mt1 = fmaxf(mt1, __shfl_xor_sync(0xffffffffu, mt1, 2));
        float mn0 = fmaxf(m0, mt0), mn1 = fmaxf(m1, mt1);
        float a0 = __expf(m0 - mn0), a1 = __expf(m1 - mn1);
        m0 = mn0; m1 = mn1;
#pragma unroll
        for (int t = 0; t < 16; t++) {
            o[t][0] *= a0; o[t][1] *= a0;
            o[t][2] *= a1; o[t][3] *= a1;
        }
        float rs0 = 0.f, rs1 = 0.f;
#pragma unroll
        for (int nj = 0; nj < 8; nj++) {
            float p0 = __expf(s_acc[nj][0] - mn0);
            float p1 = __expf(s_acc[nj][1] - mn0);
            float p2 = __expf(s_acc[nj][2] - mn1);
            float p3 = __expf(s_acc[nj][3] - mn1);
            s_acc[nj][0] = p0; s_acc[nj][1] = p1;
            s_acc[nj][2] = p2; s_acc[nj][3] = p3;
            rs0 += p0 + p1; rs1 += p2 + p3;
        }
        l0 = l0 * a0 + rs0;
        l1 = l1 * a1 + rs1;

        uint32_t ph[4][4], pl[4][4];
#pragma unroll
        for (int kc = 0; kc < 4; kc++) {
            split_pack(s_acc[2 * kc][0], s_acc[2 * kc][1], ph[kc][0], pl[kc][0]);
            split_pack(s_acc[2 * kc][2], s_acc[2 * kc][3], ph[kc][1], pl[kc][1]);
            split_pack(s_acc[2 * kc + 1][0], s_acc[2 * kc + 1][1], ph[kc][2], pl[kc][2]);
            split_pack(s_acc[2 * kc + 1][2], s_acc[2 * kc + 1][3], ph[kc][3], pl[kc][3]);
        }

#pragma unroll
        for (int njp = 0; njp < 8; njp++) {
#pragma unroll
            for (int kc = 0; kc < 4; kc++) {
                uint32_t vh4[4], vl4[4];
                ldsm_x4(sm32 + SM_VHI + v_off[njp] + kc * 32, vh4);
                ldsm_x4(sm32 + SM_VLO + v_off[njp] + kc * 32, vl4);
#pragma unroll
                for (int h = 0; h < 2; h++) {
                    int nj = njp * 2 + h;
                    mma_bf16(o[nj], ph[kc], vh4 + 2 * h);
                    mma_bf16(o[nj], ph[kc], vl4 + 2 * h);
                    mma_bf16(o[nj], pl[kc], vh4 + 2 * h);
                }
            }
        }
    }

    l0 += __shfl_xor_sync(0xffffffffu, l0, 1);
    l0 += __shfl_xor_sync(0xffffffffu, l0, 2);
    l1 += __shfl_xor_sync(0xffffffffu, l1, 1);
    l1 += __shfl_xor_sync(0xffffffffu, l1, 2);
    float i0 = 1.0f / l0, i1 = 1.0f / l1;
    int b = bh >> 4, h = bh & 15;
    int s0 = qt * 64 + warp_m + g;
    size_t r0 = ((size_t)b * SEQ + s0) * E_DIM + h * HD;
    size_t r1 = ((size_t)b * SEQ + s0 + 8) * E_DIM + h * HD;
#pragma unroll
    for (int nj = 0; nj < 16; nj++) {
        int d = nj * 8 + c * 2;
        split_store2(g_attn_hi, g_attn_lo, r0 + d, o[nj][0] * i0, o[nj][1] * i0);
        split_store2(g_attn_hi, g_attn_lo, r1 + d, o[nj][2] * i1, o[nj][3] * i1);
    }
}

// ---------------- launcher ---------------------------------------------------
extern "C" void kernel_launch(void* const* d_in, const int* in_sizes, int n_in,
                              void* d_out, int out_size) {
    const float* x = (const float*)d_in[0];
    const float* Wq = (const float*)d_in[1];
    const float* Wk = (const float*)d_in[2];
    const float* Wv = (const float*)d_in[3];
    const float* Wo = (const float*)d_in[4];
    float* out = (float*)d_out;

    cudaFuncSetAttribute(gemm_qkv_tc, cudaFuncAttributeMaxDynamicSharedMemorySize,
                         GEMM_SMEM);
    cudaFuncSetAttribute(gemm_out_tc, cudaFuncAttributeMaxDynamicSharedMemorySize,
                         GEMM_SMEM);
    cudaFuncSetAttribute(flash_mma_kernel,
                         cudaFuncAttributeMaxDynamicSharedMemorySize, FLASH_SMEM);

    rope_init_kernel<<<(SEQ * (HD / 2) + 255) / 256, 256>>>();

    {
        int n4 = MROWS * E_DIM / 4;
        convert_x_kernel<<<(n4 + 255) / 256, 256>>>((const float4*)x);
        int w4 = E_DIM * E_DIM / 4;
        dim3 gw((w4 + 255) / 256, 4);
        convert_w_kernel<<<gw, 256>>>((const float4*)Wq, (const float4*)Wk,
                                      (const float4*)Wv, (const float4*)Wo);
    }

    dim3 gqkv(E_DIM / GBN, MROWS / GBM, 3);
    gemm_qkv_tc<<<gqkv, 256, GEMM_SMEM>>>();

    dim3 gtr(SEQ / 32, HD / 32, NBATCH * NHEAD * 2);
    transpose_v_kernel<<<gtr, dim3(32, 8)>>>();

    dim3 gfa(SEQ / 64, NBATCH * NHEAD);
    flash_mma_kernel<<<gfa, 128, FLASH_SMEM>>>();

    dim3 gout(E_DIM / GBN, MROWS / GBM);
    gemm_out_tc<<<gout, 256, GEMM_SMEM>>>(out);
}

// round 9
// speedup vs baseline: 5.6516x; 1.1058x over previous
#include <cuda_runtime.h>
#include <cuda_bf16.h>
#include <math.h>
#include <stdint.h>

#define E_DIM 2048
#define SEQ 2048
#define NBATCH 2
#define NHEAD 16
#define HD 128
#define MROWS (NBATCH * SEQ) /* 4096 */

// ---------------- scratch (device globals; no allocation allowed) ----------
__device__ __nv_bfloat16 g_x_hi[MROWS * E_DIM];
__device__ __nv_bfloat16 g_x_lo[MROWS * E_DIM];
__device__ __nv_bfloat16 g_w_hi[4 * E_DIM * E_DIM];
__device__ __nv_bfloat16 g_w_lo[4 * E_DIM * E_DIM];
__device__ __nv_bfloat16 g_qhi[MROWS * E_DIM];
__device__ __nv_bfloat16 g_qlo[MROWS * E_DIM];
__device__ __nv_bfloat16 g_khi[MROWS * E_DIM];
__device__ __nv_bfloat16 g_klo[MROWS * E_DIM];
__device__ __nv_bfloat16 g_vhi[MROWS * E_DIM];
__device__ __nv_bfloat16 g_vlo[MROWS * E_DIM];
__device__ __nv_bfloat16 g_vthi[MROWS * E_DIM];
__device__ __nv_bfloat16 g_vtlo[MROWS * E_DIM];
__device__ __nv_bfloat16 g_attn_hi[MROWS * E_DIM];
__device__ __nv_bfloat16 g_attn_lo[MROWS * E_DIM];
__device__ float g_cos[SEQ * (HD / 2)];
__device__ float g_sin[SEQ * (HD / 2)];

// ---------------- helpers ----------------------------------------------------
__device__ __forceinline__ uint32_t smem_u32(const void* p) {
    uint32_t a;
    asm("{ .reg .u64 t; cvta.to.shared.u64 t, %1; cvt.u32.u64 %0, t; }"
        : "=r"(a) : "l"(p));
    return a;
}
__device__ __forceinline__ void cp_async16(uint32_t dst, const void* src) {
    asm volatile("cp.async.cg.shared.global [%0], [%1], 16;"
                 :: "r"(dst), "l"(src));
}
#define CP_COMMIT() asm volatile("cp.async.commit_group;" ::: "memory")
#define CP_WAIT2() asm volatile("cp.async.wait_group 2;" ::: "memory")
#define CP_WAIT1() asm volatile("cp.async.wait_group 1;" ::: "memory")

__device__ __forceinline__ void ldsm_x4(uint32_t addr, uint32_t* r) {
    asm volatile("ldmatrix.sync.aligned.m8n8.x4.shared.b16 {%0,%1,%2,%3}, [%4];"
                 : "=r"(r[0]), "=r"(r[1]), "=r"(r[2]), "=r"(r[3]) : "r"(addr));
}

__device__ __forceinline__ void mma_bf16(float* d, const uint32_t* a,
                                         const uint32_t* b) {
    asm volatile(
        "mma.sync.aligned.m16n8k16.row.col.f32.bf16.bf16.f32 "
        "{%0,%1,%2,%3}, {%4,%5,%6,%7}, {%8,%9}, {%0,%1,%2,%3};"
        : "+f"(d[0]), "+f"(d[1]), "+f"(d[2]), "+f"(d[3])
        : "r"(a[0]), "r"(a[1]), "r"(a[2]), "r"(a[3]), "r"(b[0]), "r"(b[1]));
}

__device__ __forceinline__ void split_pack(float x, float y, uint32_t& hi,
                                           uint32_t& lo) {
    __nv_bfloat16 hx = __float2bfloat16(x), hy = __float2bfloat16(y);
    __nv_bfloat162 h2(hx, hy);
    hi = *(uint32_t*)&h2;
    __nv_bfloat162 l2(__float2bfloat16(x - __bfloat162float(hx)),
                      __float2bfloat16(y - __bfloat162float(hy)));
    lo = *(uint32_t*)&l2;
}

__device__ __forceinline__ void split_store2(__nv_bfloat16* hi,
                                             __nv_bfloat16* lo, size_t idx,
                                             float x, float y) {
    uint32_t h, l;
    split_pack(x, y, h, l);
    *(uint32_t*)(hi + idx) = h;
    *(uint32_t*)(lo + idx) = l;
}

// ---------------- RoPE table ------------------------------------------------
__global__ void rope_init_kernel() {
    int idx = blockIdx.x * blockDim.x + threadIdx.x;
    if (idx >= SEQ * (HD / 2)) return;
    int pos = idx / (HD / 2);
    int i = idx % (HD / 2);
    double invd = pow(10000.0, -(double)(2 * i) / (double)HD);
    float inv = (float)invd;
    float ang = (float)pos * inv;
    g_cos[idx] = (float)cos((double)ang);
    g_sin[idx] = (float)sin((double)ang);
}

// ---------------- fp32 -> split bf16 conversion -----------------------------
__device__ __forceinline__ void split_store4(__nv_bfloat162* hi,
                                             __nv_bfloat162* lo, int i,
                                             float4 v) {
    __nv_bfloat16 h0 = __float2bfloat16(v.x);
    __nv_bfloat16 h1 = __float2bfloat16(v.y);
    __nv_bfloat16 h2 = __float2bfloat16(v.z);
    __nv_bfloat16 h3 = __float2bfloat16(v.w);
    hi[i * 2 + 0] = __nv_bfloat162(h0, h1);
    hi[i * 2 + 1] = __nv_bfloat162(h2, h3);
    lo[i * 2 + 0] = __nv_bfloat162(__float2bfloat16(v.x - __bfloat162float(h0)),
                                   __float2bfloat16(v.y - __bfloat162float(h1)));
    lo[i * 2 + 1] = __nv_bfloat162(__float2bfloat16(v.z - __bfloat162float(h2)),
                                   __float2bfloat16(v.w - __bfloat162float(h3)));
}

__global__ void convert_x_kernel(const float4* __restrict__ src) {
    int i = blockIdx.x * blockDim.x + threadIdx.x;
    if (i >= MROWS * E_DIM / 4) return;
    split_store4((__nv_bfloat162*)g_x_hi, (__nv_bfloat162*)g_x_lo, i, src[i]);
}

__global__ void convert_w_kernel(const float4* __restrict__ w0,
                                 const float4* __restrict__ w1,
                                 const float4* __restrict__ w2,
                                 const float4* __restrict__ w3) {
    int i = blockIdx.x * blockDim.x + threadIdx.x;
    if (i >= E_DIM * E_DIM / 4) return;
    int z = blockIdx.y;
    const float4* src = (z == 0) ? w0 : (z == 1) ? w1 : (z == 2) ? w2 : w3;
    split_store4((__nv_bfloat162*)(g_w_hi + (size_t)z * E_DIM * E_DIM),
                 (__nv_bfloat162*)(g_w_lo + (size_t)z * E_DIM * E_DIM), i, src[i]);
}

// ---------------- HMMA GEMM: cp.async 4-stage + ldmatrix --------------------
#define GBM 128
#define GBN 128
#define GBK 16
#define NCHUNK (E_DIM / GBK) /* 128 */
#define BSTR 48
#define TILE_BYTES (128 * BSTR)      /* 6144 */
#define STAGE_BYTES (4 * TILE_BYTES) /* 24576 */
#define NSTAGE 4
#define GEMM_SMEM (NSTAGE * STAGE_BYTES) /* 98304 */

// mode: 0=Q (rope+scale), 1=K (rope), 2=V, 3=fp32 out
__device__ __forceinline__ void gemm_mma_body(
    const __nv_bfloat16* __restrict__ Ahi, const __nv_bfloat16* __restrict__ Alo,
    const __nv_bfloat16* __restrict__ Bhi, const __nv_bfloat16* __restrict__ Blo,
    float* __restrict__ Cout, int mode) {
    extern __shared__ char smem[];
    uint32_t sbase = smem_u32(smem);
    int tid = threadIdx.x;
    int wid = tid >> 5;
    int lane = tid & 31;
    int m0 = blockIdx.y * GBM;
    int n0 = blockIdx.x * GBN;
    int warp_m = (wid & 3) * 32;
    int warp_n = (wid >> 2) * 64;

    int gidx = lane >> 2;

    int a_row = (lane & 7) + ((lane >> 3) & 1) * 8;
    int a_col = (lane >> 4) * 16;
    uint32_t a_off[2];
#pragma unroll
    for (int mi = 0; mi < 2; mi++)
        a_off[mi] = (uint32_t)((warp_m + mi * 16 + a_row) * BSTR + a_col);
    int b_row = (lane & 7) + ((lane >> 4) & 1) * 8;
    int b_col = ((lane >> 3) & 1) * 16;
    uint32_t b_off[4];
#pragma unroll
    for (int njp = 0; njp < 4; njp++)
        b_off[njp] = (uint32_t)((warp_n + njp * 16 + b_row) * BSTR + b_col);

    int row = tid >> 1;
    int ce = (tid & 1) * 8;
    uint32_t soff = (uint32_t)(row * BSTR + (tid & 1) * 16);
    const __nv_bfloat16* pa_hi = Ahi + (size_t)(m0 + row) * E_DIM + ce;
    const __nv_bfloat16* pa_lo = Alo + (size_t)(m0 + row) * E_DIM + ce;
    const __nv_bfloat16* pb_hi = Bhi + (size_t)(n0 + row) * E_DIM + ce;
    const __nv_bfloat16* pb_lo = Blo + (size_t)(n0 + row) * E_DIM + ce;

    float acc[2][8][4];
#pragma unroll
    for (int mi = 0; mi < 2; mi++)
#pragma unroll
        for (int nj = 0; nj < 8; nj++)
#pragma unroll
            for (int q = 0; q < 4; q++) acc[mi][nj][q] = 0.f;

#pragma unroll
    for (int s = 0; s < NSTAGE - 1; s++) {
        uint32_t st = sbase + s * STAGE_BYTES + soff;
        int k0 = s * GBK;
        cp_async16(st + 0 * TILE_BYTES, pa_hi + k0);
        cp_async16(st + 1 * TILE_BYTES, pa_lo + k0);
        cp_async16(st + 2 * TILE_BYTES, pb_hi + k0);
        cp_async16(st + 3 * TILE_BYTES, pb_lo + k0);
        CP_COMMIT();
    }

    for (int c = 0; c < NCHUNK; c++) {
        CP_WAIT2();
        __syncthreads();

        uint32_t st = sbase + (uint32_t)(c & (NSTAGE - 1)) * STAGE_BYTES;

        uint32_t ahi[2][4], alo[2][4];
#pragma unroll
        for (int mi = 0; mi < 2; mi++) {
            ldsm_x4(st + a_off[mi], ahi[mi]);
            ldsm_x4(st + TILE_BYTES + a_off[mi], alo[mi]);
        }
#pragma unroll
        for (int njp = 0; njp < 4; njp++) {
            uint32_t bh4[4], bl4[4];
            ldsm_x4(st + 2 * TILE_BYTES + b_off[njp], bh4);
            ldsm_x4(st + 3 * TILE_BYTES + b_off[njp], bl4);
            int nj0 = njp * 2, nj1 = njp * 2 + 1;
            // term-outer: consecutive MMAs hit different accumulators
            mma_bf16(acc[0][nj0], ahi[0], bh4 + 0);
            mma_bf16(acc[1][nj0], ahi[1], bh4 + 0);
            mma_bf16(acc[0][nj1], ahi[0], bh4 + 2);
            mma_bf16(acc[1][nj1], ahi[1], bh4 + 2);
            mma_bf16(acc[0][nj0], ahi[0], bl4 + 0);
            mma_bf16(acc[1][nj0], ahi[1], bl4 + 0);
            mma_bf16(acc[0][nj1], ahi[0], bl4 + 2);
            mma_bf16(acc[1][nj1], ahi[1], bl4 + 2);
            mma_bf16(acc[0][nj0], alo[0], bh4 + 0);
            mma_bf16(acc[1][nj0], alo[1], bh4 + 0);
            mma_bf16(acc[0][nj1], alo[0], bh4 + 2);
            mma_bf16(acc[1][nj1], alo[1], bh4 + 2);
        }

        if (c + NSTAGE - 1 < NCHUNK) {
            uint32_t sw = sbase + ((c + NSTAGE - 1) & (NSTAGE - 1)) * STAGE_BYTES + soff;
            int k0 = (c + NSTAGE - 1) * GBK;
            cp_async16(sw + 0 * TILE_BYTES, pa_hi + k0);
            cp_async16(sw + 1 * TILE_BYTES, pa_lo + k0);
            cp_async16(sw + 2 * TILE_BYTES, pb_hi + k0);
            cp_async16(sw + 3 * TILE_BYTES, pb_lo + k0);
        }
        CP_COMMIT();
    }

    int tig = lane & 3;
    __nv_bfloat16* dhi = (mode == 0) ? g_qhi : (mode == 1) ? g_khi : g_vhi;
    __nv_bfloat16* dlo = (mode == 0) ? g_qlo : (mode == 1) ? g_klo : g_vlo;
    const float qsc = (mode == 0) ? 0.08838834764831845f : 1.0f;

#pragma unroll
    for (int mi = 0; mi < 2; mi++) {
#pragma unroll
        for (int nj = 0; nj < 8; nj++) {
            int m = m0 + warp_m + mi * 16 + gidx;
            int n = n0 + warp_n + nj * 8 + tig * 2;
            float v0 = acc[mi][nj][0], v1 = acc[mi][nj][1];
            float v2 = acc[mi][nj][2], v3 = acc[mi][nj][3];
            if (mode <= 1) {
                int pi = (n & (HD - 1)) >> 1;
                int p0 = m & (SEQ - 1);
                int p8 = p0 + 8;
                float c0 = g_cos[p0 * (HD / 2) + pi], s0 = g_sin[p0 * (HD / 2) + pi];
                float c8 = g_cos[p8 * (HD / 2) + pi], s8 = g_sin[p8 * (HD / 2) + pi];
                float t0 = v0 * c0 - v1 * s0, t1 = v0 * s0 + v1 * c0;
                float t2 = v2 * c8 - v3 * s8, t3 = v2 * s8 + v3 * c8;
                v0 = t0 * qsc; v1 = t1 * qsc; v2 = t2 * qsc; v3 = t3 * qsc;
            }
            if (mode == 3) {
                *(float2*)&Cout[(size_t)m * E_DIM + n] = make_float2(v0, v1);
                *(float2*)&Cout[(size_t)(m + 8) * E_DIM + n] = make_float2(v2, v3);
            } else {
                int b = m >> 11, s = m & 2047, h = n >> 7, d = n & 127;
                size_t base0 = ((size_t)(b * NHEAD + h) * SEQ + s) * HD + d;
                size_t base1 = base0 + 8 * HD;
                split_store2(dhi, dlo, base0, v0, v1);
                split_store2(dhi, dlo, base1, v2, v3);
            }
        }
    }
}

__global__ __launch_bounds__(256, 2) void gemm_qkv_tc(void) {
    int z = blockIdx.z;
    const __nv_bfloat16* bh = g_w_hi + (size_t)z * E_DIM * E_DIM;
    const __nv_bfloat16* bl = g_w_lo + (size_t)z * E_DIM * E_DIM;
    gemm_mma_body(g_x_hi, g_x_lo, bh, bl, nullptr, z);
}

__global__ __launch_bounds__(256, 2) void gemm_out_tc(float* __restrict__ out) {
    const __nv_bfloat16* bh = g_w_hi + (size_t)3 * E_DIM * E_DIM;
    const __nv_bfloat16* bl = g_w_lo + (size_t)3 * E_DIM * E_DIM;
    gemm_mma_body(g_attn_hi, g_attn_lo, bh, bl, out, 3);
}

// ---------------- V transpose: [bh][s][d] -> [bh][d][s] ---------------------
__global__ void transpose_v_kernel() {
    __shared__ __nv_bfloat16 t[32][33];
    int bh = blockIdx.z >> 1;
    const __nv_bfloat16* src = (blockIdx.z & 1) ? g_vlo : g_vhi;
    __nv_bfloat16* dst = (blockIdx.z & 1) ? g_vtlo : g_vthi;
    int tx = threadIdx.x, ty = threadIdx.y;
    int s0 = blockIdx.x * 32, d0 = blockIdx.y * 32;
#pragma unroll
    for (int i = 0; i < 32; i += 8)
        t[ty + i][tx] = src[((size_t)bh * SEQ + s0 + ty + i) * HD + d0 + tx];
    __syncthreads();
#pragma unroll
    for (int i = 0; i < 32; i += 8)
        dst[((size_t)bh * HD + d0 + ty + i) * SEQ + s0 + tx] = t[tx][ty + i];
}

// ---------------- Tensor-core flash attention (causal, cp.async DB) ---------
// 4 warps, q-tile 64, k-tile 32, 2-stage double buffer.
#define KSTR2 272 /* K row stride bytes */
#define VSTR2 80  /* Vt row stride bytes (32 bf16 + pad) */
#define F_KHI 0
#define F_KLO 8704                  /* 32*272 */
#define F_VHI (2 * 8704)            /* 17408 */
#define F_VLO (F_VHI + 128 * VSTR2) /* 27648 */
#define F_STAGE (F_VLO + 128 * VSTR2) /* 37888 */
#define FLASH_SMEM (2 * F_STAGE)      /* 75776 */

__device__ __forceinline__ void flash_stage_load(
    uint32_t sst, const __nv_bfloat16* Kh, const __nv_bfloat16* Kl,
    const __nv_bfloat16* Vh, const __nv_bfloat16* Vl, int kt2, int tid) {
    int k0 = kt2 * 32;
#pragma unroll
    for (int i = 0; i < 4; i++) {
        int idx = tid + i * 128;
        int row = idx >> 4, cc = idx & 15;
        uint32_t d = sst + (uint32_t)(row * KSTR2 + cc * 16);
        cp_async16(d + F_KHI, Kh + (size_t)(k0 + row) * HD + cc * 8);
        cp_async16(d + F_KLO, Kl + (size_t)(k0 + row) * HD + cc * 8);
    }
#pragma unroll
    for (int i = 0; i < 4; i++) {
        int idx = tid + i * 128;
        int row = idx >> 2, cc = idx & 3;
        uint32_t d = sst + (uint32_t)(row * VSTR2 + cc * 16);
        cp_async16(d + F_VHI, Vh + (size_t)row * SEQ + k0 + cc * 8);
        cp_async16(d + F_VLO, Vl + (size_t)row * SEQ + k0 + cc * 8);
    }
}

__global__ __launch_bounds__(128) void flash_mma_kernel() {
    extern __shared__ char sm[];
    uint32_t sm32 = smem_u32(sm);

    int tid = threadIdx.x;
    int wid = tid >> 5;
    int lane = tid & 31;
    int qt = (int)gridDim.x - 1 - (int)blockIdx.x;  // heavy tiles first
    int bh = blockIdx.y;
    int g = lane >> 2;
    int c = lane & 3;
    int warp_m = wid * 16;
    int nkt = 2 * (qt + 1);

    // ldmatrix lane offsets (B-operand pattern)
    int b_row = (lane & 7) + ((lane >> 4) & 1) * 8;
    int b_col = ((lane >> 3) & 1) * 16;
    uint32_t k_off[2], v_off[8];
#pragma unroll
    for (int njp = 0; njp < 2; njp++)
        k_off[njp] = (uint32_t)((njp * 16 + b_row) * KSTR2 + b_col);
#pragma unroll
    for (int njp = 0; njp < 8; njp++)
        v_off[njp] = (uint32_t)((njp * 16 + b_row) * VSTR2 + b_col);

    const __nv_bfloat16* Kh = g_khi + (size_t)bh * SEQ * HD;
    const __nv_bfloat16* Kl = g_klo + (size_t)bh * SEQ * HD;
    const __nv_bfloat16* Vh = g_vthi + (size_t)bh * HD * SEQ;
    const __nv_bfloat16* Vl = g_vtlo + (size_t)bh * HD * SEQ;

    // prologue: stage 0 in flight while we load Q fragments
    flash_stage_load(sm32, Kh, Kl, Vh, Vl, 0, tid);
    CP_COMMIT();

    uint32_t qh[8][4], ql[8][4];
    {
        const __nv_bfloat16* Qh = g_qhi + (size_t)bh * SEQ * HD + (size_t)qt * 64 * HD;
        const __nv_bfloat16* Ql = g_qlo + (size_t)bh * SEQ * HD + (size_t)qt * 64 * HD;
        int r0 = (warp_m + g) * HD, r1 = (warp_m + g + 8) * HD;
#pragma unroll
        for (int kc = 0; kc < 8; kc++) {
            int c0 = kc * 16 + c * 2, c1 = c0 + 8;
            qh[kc][0] = *(const uint32_t*)(Qh + r0 + c0);
            qh[kc][1] = *(const uint32_t*)(Qh + r1 + c0);
            qh[kc][2] = *(const uint32_t*)(Qh + r0 + c1);
            qh[kc][3] = *(const uint32_t*)(Qh + r1 + c1);
            ql[kc][0] = *(const uint32_t*)(Ql + r0 + c0);
            ql[kc][1] = *(const uint32_t*)(Ql + r1 + c0);
            ql[kc][2] = *(const uint32_t*)(Ql + r0 + c1);
            ql[kc][3] = *(const uint32_t*)(Ql + r1 + c1);
        }
    }

    float o[16][4];
#pragma unroll
    for (int t = 0; t < 16; t++)
#pragma unroll
        for (int q = 0; q < 4; q++) o[t][q] = 0.f;
    float m0 = -1e30f, m1 = -1e30f, l0 = 0.f, l1 = 0.f;

    for (int kt2 = 0; kt2 < nkt; kt2++) {
        // issue next stage (other buffer; safe: trailing barrier of prev iter)
        if (kt2 + 1 < nkt)
            flash_stage_load(sm32 + ((kt2 + 1) & 1) * F_STAGE, Kh, Kl, Vh, Vl,
                             kt2 + 1, tid);
        CP_COMMIT();
        CP_WAIT1();
        __syncthreads();

        uint32_t st = sm32 + (uint32_t)(kt2 & 1) * F_STAGE;

        // ---- S = Q @ K^T (16q x 32k per warp) ----
        float s_acc[4][4];
#pragma unroll
        for (int nj = 0; nj < 4; nj++)
#pragma unroll
            for (int q = 0; q < 4; q++) s_acc[nj][q] = 0.f;

#pragma unroll
        for (int kc = 0; kc < 8; kc++) {
#pragma unroll
            for (int njp = 0; njp < 2; njp++) {
                uint32_t bh4[4], bl4[4];
                ldsm_x4(st + F_KHI + k_off[njp] + kc * 32, bh4);
                ldsm_x4(st + F_KLO + k_off[njp] + kc * 32, bl4);
                int nj0 = njp * 2, nj1 = njp * 2 + 1;
                mma_bf16(s_acc[nj0], qh[kc], bh4 + 0);
                mma_bf16(s_acc[nj1], qh[kc], bh4 + 2);
                mma_bf16(s_acc[nj0], qh[kc], bl4 + 0);
                mma_bf16(s_acc[nj1], qh[kc], bl4 + 2);
                mma_bf16(s_acc[nj0], ql[kc], bh4 + 0);
                mma_bf16(s_acc[nj1], ql[kc], bh4 + 2);
            }
        }

        // ---- causal mask (diagonal k-tiles only) ----
        if (kt2 >= 2 * qt) {
            int row0 = qt * 64 + warp_m + g, row1 = row0 + 8;
            int colb = kt2 * 32;
#pragma unroll
            for (int nj = 0; nj < 4; nj++) {
                int col = colb + nj * 8 + c * 2;
                if (col > row0) s_acc[nj][0] = -1e30f;
                if (col + 1 > row0) s_acc[nj][1] = -1e30f;
                if (col > row1) s_acc[nj][2] = -1e30f;
                if (col + 1 > row1) s_acc[nj][3] = -1e30f;
            }
        }

        // ---- online softmax ----
        float mt0 = -1e30f, mt1 = -1e30f;
#pragma unroll
        for (int nj = 0; nj < 4; nj++) {
            mt0 = fmaxf(mt0, fmaxf(s_acc[nj][0], s_acc[nj][1]));
            mt1 = fmaxf(mt1, fmaxf(s_acc[nj][2], s_acc[nj][3]));
        }
        mt0 = fmaxf(mt0, __shfl_xor_sync(0xffffffffu, mt0, 1));
        mt0 = fmaxf(mt0, __shfl_xor_sync(0xffffffffu, mt0, 2));
        mt1 = fmaxf(mt1, __shfl_xor_sync(0xffffffffu, mt1, 1));
        mt1 = fmaxf(mt1, __shfl_xor_sync(0xffffffffu, mt1, 2));
        float mn0 = fmaxf(m0, mt0), mn1 = fmaxf(m1, mt1);
        float a0 = __expf(m0 - mn0), a1 = __expf(m1 - mn1);
        m0 = mn0; m1 = mn1;
#pragma unroll
        for (int t = 0; t < 16; t++) {
            o[t][0] *= a0; o[t][1] *= a0;
            o[t][2] *= a1; o[t][3] *= a1;
        }
        float rs0 = 0.f, rs1 = 0.f;
#pragma unroll
        for (int nj = 0; nj < 4; nj++) {
            float p0 = __expf(s_acc[nj][0] - mn0);
            float p1 = __expf(s_acc[nj][1] - mn0);
            float p2 = __expf(s_acc[nj][2] - mn1);
            float p3 = __expf(s_acc[nj][3] - mn1);
            s_acc[nj][0] = p0; s_acc[nj][1] = p1;
            s_acc[nj][2] = p2; s_acc[nj][3] = p3;
            rs0 += p0 + p1; rs1 += p2 + p3;
        }
        l0 = l0 * a0 + rs0;
        l1 = l1 * a1 + rs1;

        // ---- P fragments (A-layout) ----
        uint32_t ph[2][4], pl[2][4];
#pragma unroll
        for (int kc = 0; kc < 2; kc++) {
            split_pack(s_acc[2 * kc][0], s_acc[2 * kc][1], ph[kc][0], pl[kc][0]);
            split_pack(s_acc[2 * kc][2], s_acc[2 * kc][3], ph[kc][1], pl[kc][1]);
            split_pack(s_acc[2 * kc + 1][0], s_acc[2 * kc + 1][1], ph[kc][2], pl[kc][2]);
            split_pack(s_acc[2 * kc + 1][2], s_acc[2 * kc + 1][3], ph[kc][3], pl[kc][3]);
        }

        // ---- O += P @ V ----
#pragma unroll
        for (int njp = 0; njp < 8; njp++) {
#pragma unroll
            for (int kc = 0; kc < 2; kc++) {
                uint32_t vh4[4], vl4[4];
                ldsm_x4(st + F_VHI + v_off[njp] + kc * 32, vh4);
                ldsm_x4(st + F_VLO + v_off[njp] + kc * 32, vl4);
                int nj0 = njp * 2, nj1 = njp * 2 + 1;
                mma_bf16(o[nj0], ph[kc], vh4 + 0);
                mma_bf16(o[nj1], ph[kc], vh4 + 2);
                mma_bf16(o[nj0], ph[kc], vl4 + 0);
                mma_bf16(o[nj1], ph[kc], vl4 + 2);
                mma_bf16(o[nj0], pl[kc], vh4 + 0);
                mma_bf16(o[nj1], pl[kc], vh4 + 2);
            }
        }
        __syncthreads();  // all reads of this stage done before it is rewritten
    }

    l0 += __shfl_xor_sync(0xffffffffu, l0, 1);
    l0 += __shfl_xor_sync(0xffffffffu, l0, 2);
    l1 += __shfl_xor_sync(0xffffffffu, l1, 1);
    l1 += __shfl_xor_sync(0xffffffffu, l1, 2);
    float i0 = 1.0f / l0, i1 = 1.0f / l1;
    int b = bh >> 4, h = bh & 15;
    int s0 = qt * 64 + warp_m + g;
    size_t r0 = ((size_t)b * SEQ + s0) * E_DIM + h * HD;
    size_t r1 = ((size_t)b * SEQ + s0 + 8) * E_DIM + h * HD;
#pragma unroll
    for (int nj = 0; nj < 16; nj++) {
        int d = nj * 8 + c * 2;
        split_store2(g_attn_hi, g_attn_lo, r0 + d, o[nj][0] * i0, o[nj][1] * i0);
        split_store2(g_attn_hi, g_attn_lo, r1 + d, o[nj][2] * i1, o[nj][3] * i1);
    }
}

// ---------------- launcher ---------------------------------------------------
extern "C" void kernel_launch(void* const* d_in, const int* in_sizes, int n_in,
                              void* d_out, int out_size) {
    const float* x = (const float*)d_in[0];
    const float* Wq = (const float*)d_in[1];
    const float* Wk = (const float*)d_in[2];
    const float* Wv = (const float*)d_in[3];
    const float* Wo = (const float*)d_in[4];
    float* out = (float*)d_out;

    cudaFuncSetAttribute(gemm_qkv_tc, cudaFuncAttributeMaxDynamicSharedMemorySize,
                         GEMM_SMEM);
    cudaFuncSetAttribute(gemm_out_tc, cudaFuncAttributeMaxDynamicSharedMemorySize,
                         GEMM_SMEM);
    cudaFuncSetAttribute(flash_mma_kernel,
                         cudaFuncAttributeMaxDynamicSharedMemorySize, FLASH_SMEM);

    rope_init_kernel<<<(SEQ * (HD / 2) + 255) / 256, 256>>>();

    {
        int n4 = MROWS * E_DIM / 4;
        convert_x_kernel<<<(n4 + 255) / 256, 256>>>((const float4*)x);
        int w4 = E_DIM * E_DIM / 4;
        dim3 gw((w4 + 255) / 256, 4);
        convert_w_kernel<<<gw, 256>>>((const float4*)Wq, (const float4*)Wk,
                                      (const float4*)Wv, (const float4*)Wo);
    }

    dim3 gqkv(E_DIM / GBN, MROWS / GBM, 3);
    gemm_qkv_tc<<<gqkv, 256, GEMM_SMEM>>>();

    dim3 gtr(SEQ / 32, HD / 32, NBATCH * NHEAD * 2);
    transpose_v_kernel<<<gtr, dim3(32, 8)>>>();

    dim3 gfa(SEQ / 64, NBATCH * NHEAD);
    flash_mma_kernel<<<gfa, 128, FLASH_SMEM>>>();

    dim3 gout(E_DIM / GBN, MROWS / GBM);
    gemm_out_tc<<<gout, 256, GEMM_SMEM>>>(out);
}